// round 12
// baseline (speedup 1.0000x reference)
#include <cuda_runtime.h>
#include <cuda_bf16.h>
#include <cstdint>

// ---------------- problem constants ----------------
constexpr int KT = 4, KB = 16, KC = 384, KN = 256, KH = 8, KD = 48;
constexpr int COLS = KT * KB * KN;     // 16384
constexpr int TCOL = KB * KN;          // 4096
constexpr int SZ_XT = KC * TCOL;       // 1,572,864
constexpr int SZ_X  = KC * COLS;       // 6,291,456
constexpr long long SZ_ATT = (long long)KT * KB * KH * KN * KN;   // 33,554,432

// ---------------- device scratch ----------------
__device__ __align__(16) float g_qkv[3 * SZ_X];     // q|k|v fp32, blocked [c][t*4096+b*256+n]
__device__ __align__(16) float g_cb [SZ_XT];        // tim conv out (raw conv of z)
__device__ __align__(16) float g_o  [SZ_X];         // out + identity, blocked fp32
__device__ __align__(16) float g_p  [SZ_X];         // proj pre-act [c][16384]

__device__ __align__(16) int8_t g_xs8[SZ_X];        // shortcut spikes s8 [c][16384]
__device__ __align__(16) int8_t g_xsT[SZ_X];        // transposed      [j][c]
__device__ __align__(16) int8_t g_z8 [SZ_XT];       // tim z state s8 [c][4096]
__device__ __align__(16) int8_t g_zT [SZ_XT];       // transposed     [j][c]
__device__ __align__(16) int8_t g_w8q[1152 * 1536]; // qkv weight digits [r][dig*384+c]
__device__ __align__(16) int8_t g_w8t[384 * 7680];  // tim weight digits [r][dig*1920+kk*384+ci]
__device__ float g_sqkv[1152], g_stim[384];

__device__ __align__(16) __nv_bfloat16 g_qhT [SZ_X];   // q heads bf16 [z][d][n]
__device__ __align__(16) __nv_bfloat16 g_amap[SZ_ATT]; // attn map bf16 [z][m][n]
__device__ __align__(16) __nv_bfloat16 g_kt3[512 * 256 * 144];
__device__ __align__(16) __nv_bfloat16 g_vt3[512 * 48 * 768];

__device__ __align__(16) float g_wqkv[3 * KC * KC];
__device__ float g_bqkv[3 * KC];
__device__ __align__(16) float g_wpf[KC * KC];
__device__ float g_bp[KC];
__device__ float g_dw[KD * KD], g_dwT[KD * KD], g_db[KD];
__device__ float g_cnt[1], g_c1[1];

// ---------------- mma helpers ----------------
__device__ __forceinline__ void ldm_x4(uint32_t& r0, uint32_t& r1, uint32_t& r2, uint32_t& r3, uint32_t addr)
{
    asm volatile("ldmatrix.sync.aligned.m8n8.x4.shared.b16 {%0,%1,%2,%3}, [%4];"
                 : "=r"(r0), "=r"(r1), "=r"(r2), "=r"(r3) : "r"(addr));
}
__device__ __forceinline__ void ldm_x2(uint32_t& r0, uint32_t& r1, uint32_t addr)
{
    asm volatile("ldmatrix.sync.aligned.m8n8.x2.shared.b16 {%0,%1}, [%2];"
                 : "=r"(r0), "=r"(r1) : "r"(addr));
}
__device__ __forceinline__ void ldm_x2t(uint32_t& r0, uint32_t& r1, uint32_t addr)
{
    asm volatile("ldmatrix.sync.aligned.m8n8.x2.trans.shared.b16 {%0,%1}, [%2];"
                 : "=r"(r0), "=r"(r1) : "r"(addr));
}
__device__ __forceinline__ void mma_bf16(float* c, const uint32_t* a, const uint32_t* b)
{
    asm volatile("mma.sync.aligned.m16n8k16.row.col.f32.bf16.bf16.f32 "
                 "{%0,%1,%2,%3}, {%4,%5,%6,%7}, {%8,%9}, {%0,%1,%2,%3};"
                 : "+f"(c[0]), "+f"(c[1]), "+f"(c[2]), "+f"(c[3])
                 : "r"(a[0]), "r"(a[1]), "r"(a[2]), "r"(a[3]), "r"(b[0]), "r"(b[1]));
}
__device__ __forceinline__ void mma_s8(int* c, const uint32_t* a, const uint32_t* b)
{
    asm volatile("mma.sync.aligned.m16n8k32.row.col.s32.s8.s8.s32 "
                 "{%0,%1,%2,%3}, {%4,%5,%6,%7}, {%8,%9}, {%0,%1,%2,%3};"
                 : "+r"(c[0]), "+r"(c[1]), "+r"(c[2]), "+r"(c[3])
                 : "r"(a[0]), "r"(a[1]), "r"(a[2]), "r"(a[3]), "r"(b[0]), "r"(b[1]));
}

// ---------------- s8 digit GEMM ----------------
// C[M,N] = S_r * sum_dig 2^(-6-7dig) * (Adig[M,Kd] . B[N,Kd]^T) (+bias)
// A: s8 [M][4*Kd] (digit-major blocks). B: BMODE0: s8 [N][Kd] n-major.
// BMODE1 (TIM conv): B row j, col kk*384+ci -> zT[j+kk-2][ci], masked at n-boundary.
template<int BMODE, int HASB>
__global__ void __launch_bounds__(256, 2)
gemm_s8(int Kd,
        const int8_t* __restrict__ A, int lda,
        const int8_t* __restrict__ B,
        float* __restrict__ C, int ldc,
        const float* __restrict__ scl, const float* __restrict__ bias)
{
    constexpr int BM = 128, BN = 64, BK = 64;
    constexpr int ASTR = BK + 16;   // 80-byte rows: conflict-free ldmatrix
    __shared__ __align__(16) int8_t As[2][BM * ASTR];
    __shared__ __align__(16) int8_t Bs[2][BN * ASTR];
    const int tid = threadIdx.x, wid = tid >> 5, lane = tid & 31;
    const int wm = (wid >> 1) * 32, wn = (wid & 1) * 32;    // 4 warps M x 2 warps N
    const int row0 = blockIdx.y * BM, col0 = blockIdx.x * BN;
    const int KT64 = Kd / 64;
    const int NIT = 4 * KT64;

    uint4 ar[2], br;
    auto ldg = [&](int it) {
#pragma unroll
        for (int u = 0; u < 2; u++) {
            int idx = tid + u * 256;
            int r = idx >> 2, c16 = idx & 3;
            ar[u] = *(const uint4*)&A[(long long)(row0 + r) * lda + it * 64 + c16 * 16];
        }
        int k0 = (it % KT64) * 64;
        int n = tid >> 2, c16 = tid & 3;
        if (BMODE == 0) {
            br = *(const uint4*)&B[(long long)(col0 + n) * Kd + k0 + c16 * 16];
        } else {
            int kk = k0 / 384, ci = k0 - kk * 384;
            int j = col0 + n;
            int n2 = (j & 255) + kk - 2;
            if (n2 >= 0 && n2 < 256)
                br = *(const uint4*)&B[(long long)(j + kk - 2) * 384 + ci + c16 * 16];
            else
                br = make_uint4(0u, 0u, 0u, 0u);
        }
    };
    auto sts = [&](int buf) {
#pragma unroll
        for (int u = 0; u < 2; u++) {
            int idx = tid + u * 256;
            int r = idx >> 2, c16 = idx & 3;
            *(uint4*)&As[buf][r * ASTR + c16 * 16] = ar[u];
        }
        int n = tid >> 2, c16 = tid & 3;
        *(uint4*)&Bs[buf][n * ASTR + c16 * 16] = br;
    };

    float accF[2][4][4];
    int   accS[2][4][4];
#pragma unroll
    for (int i = 0; i < 2; i++)
#pragma unroll
        for (int j = 0; j < 4; j++)
#pragma unroll
            for (int q = 0; q < 4; q++) { accF[i][j][q] = 0.f; accS[i][j][q] = 0; }

    auto comp = [&](int buf) {
#pragma unroll
        for (int s = 0; s < 2; s++) {
            uint32_t af[2][4], bf[4][2];
#pragma unroll
            for (int mi = 0; mi < 2; mi++) {
                int row = wm + mi * 16 + (lane & 15);
                int col = s * 32 + (lane >> 4) * 16;
                uint32_t ad = (uint32_t)__cvta_generic_to_shared(&As[buf][row * ASTR + col]);
                ldm_x4(af[mi][0], af[mi][1], af[mi][2], af[mi][3], ad);
            }
#pragma unroll
            for (int nj = 0; nj < 4; nj++) {
                int n = wn + nj * 8 + (lane & 7);
                int col = s * 32 + ((lane >> 3) & 1) * 16;
                uint32_t ad = (uint32_t)__cvta_generic_to_shared(&Bs[buf][n * ASTR + col]);
                ldm_x2(bf[nj][0], bf[nj][1], ad);
            }
#pragma unroll
            for (int mi = 0; mi < 2; mi++)
#pragma unroll
                for (int nj = 0; nj < 4; nj++)
                    mma_s8(accS[mi][nj], af[mi], bf[nj]);
        }
    };
    const float fd[4] = {0x1p-6f, 0x1p-13f, 0x1p-20f, 0x1p-27f};
    int kcnt = 0, dig = 0;
    auto fold = [&]() {
        kcnt++;
        if (kcnt == KT64) {
            float w = fd[dig];
#pragma unroll
            for (int i = 0; i < 2; i++)
#pragma unroll
                for (int j = 0; j < 4; j++)
#pragma unroll
                    for (int q = 0; q < 4; q++) {
                        accF[i][j][q] += (float)accS[i][j][q] * w;
                        accS[i][j][q] = 0;
                    }
            kcnt = 0; dig++;
        }
    };

    ldg(0); sts(0); __syncthreads();
    int buf = 0;
    for (int it = 1; it < NIT; it++) {
        ldg(it);
        comp(buf);
        fold();
        sts(buf ^ 1);
        __syncthreads();
        buf ^= 1;
    }
    comp(buf);
    fold();

#pragma unroll
    for (int mi = 0; mi < 2; mi++) {
        int r0 = row0 + wm + mi * 16 + (lane >> 2);
        float s0 = scl[r0], s1 = scl[r0 + 8];
        float b0 = HASB ? bias[r0] : 0.f;
        float b1 = HASB ? bias[r0 + 8] : 0.f;
#pragma unroll
        for (int nj = 0; nj < 4; nj++) {
            int c0 = col0 + wn + nj * 8 + (lane & 3) * 2;
            float2 v0 = {accF[mi][nj][0] * s0 + b0, accF[mi][nj][1] * s0 + b0};
            float2 v1 = {accF[mi][nj][2] * s1 + b1, accF[mi][nj][3] * s1 + b1};
            *(float2*)&C[(long long)r0 * ldc + c0] = v0;
            *(float2*)&C[(long long)(r0 + 8) * ldc + c0] = v1;
        }
    }
}

// ---------------- s8 transpose (32x32 tiles) ----------------
__global__ void transpose8(const int8_t* __restrict__ in, int8_t* __restrict__ out, int R, int C)
{
    __shared__ int8_t tile[32][33];
    int c0 = blockIdx.x * 32, r0 = blockIdx.y * 32;
    int tx = threadIdx.x, ty = threadIdx.y;
#pragma unroll
    for (int k = 0; k < 32; k += 8)
        tile[ty + k][tx] = in[(long long)(r0 + ty + k) * C + c0 + tx];
    __syncthreads();
#pragma unroll
    for (int k = 0; k < 32; k += 8)
        out[(long long)(c0 + ty + k) * R + r0 + tx] = tile[tx][ty + k];
}

// ---------------- weight digitization ----------------
__global__ void rowscale(const float* __restrict__ w, int cols, float* __restrict__ scl)
{
    __shared__ float sm[256];
    int r = blockIdx.x;
    float m = 0.f;
    for (int c = threadIdx.x; c < cols; c += 256)
        m = fmaxf(m, fabsf(w[(long long)r * cols + c]));
    sm[threadIdx.x] = m;
    __syncthreads();
    for (int o = 128; o > 0; o >>= 1) {
        if (threadIdx.x < o) sm[threadIdx.x] = fmaxf(sm[threadIdx.x], sm[threadIdx.x + o]);
        __syncthreads();
    }
    if (threadIdx.x == 0) {
        float mv = sm[0];
        scl[r] = (mv > 0.f) ? exp2f(ceilf(log2f(mv))) : 1.f;
    }
}

__device__ __forceinline__ void dig4(float v, int8_t* d)
{
    float d0 = rintf(v * 64.f);            float r1 = v  - d0 * 0x1p-6f;
    float d1 = rintf(r1 * 0x1p13f);        float r2 = r1 - d1 * 0x1p-13f;
    float d2 = rintf(r2 * 0x1p20f);        float r3 = r2 - d2 * 0x1p-20f;
    float d3 = rintf(r3 * 0x1p27f);
    d[0] = (int8_t)(int)d0; d[1] = (int8_t)(int)d1;
    d[2] = (int8_t)(int)d2; d[3] = (int8_t)(int)d3;
}

__global__ void split8_qkv()
{
    int i = blockIdx.x * blockDim.x + threadIdx.x;
    if (i >= 1152 * 384) return;
    int r = i / 384, c = i % 384;
    int8_t d[4];
    dig4(g_wqkv[i] / g_sqkv[r], d);
    int8_t* row = g_w8q + (long long)r * 1536;
    row[c] = d[0]; row[384 + c] = d[1]; row[768 + c] = d[2]; row[1152 + c] = d[3];
}

__global__ void split8_tim(const float* __restrict__ timw)
{
    int i = blockIdx.x * blockDim.x + threadIdx.x;
    if (i >= 384 * 1920) return;
    int co = i / 1920, rem = i % 1920;
    int ci = rem / 5, kk = rem % 5;
    int8_t d[4];
    dig4(timw[i] / g_stim[co], d);
    int8_t* row = g_w8t + (long long)co * 7680;
    int cc = kk * 384 + ci;
    row[cc] = d[0]; row[1920 + cc] = d[1]; row[3840 + cc] = d[2]; row[5760 + cc] = d[3];
}

// ---------------- BN folding ----------------
__global__ void fold_weights(const float* __restrict__ wq, const float* __restrict__ wk,
                             const float* __restrict__ wv, const float* __restrict__ pw,
                             const float* __restrict__ pb, const float* __restrict__ kbn,
                             const float* __restrict__ vbn, const float* __restrict__ pbn,
                             const float* __restrict__ dstw, const float* __restrict__ dbn)
{
    int i = blockIdx.x * blockDim.x + threadIdx.x;
    if (i == 0) g_cnt[0] = 0.f;
    if (i < 3 * KC * KC) {
        int rr = i / KC, c = i % KC;
        float w;
        if (rr < KC) w = wq[rr * KC + c];
        else if (rr < 2 * KC) { int d = rr - KC;     w = kbn[d] * rsqrtf(kbn[3*KC + d] + 1e-5f) * wk[d * KC + c]; }
        else                  { int d = rr - 2 * KC; w = vbn[d] * rsqrtf(vbn[3*KC + d] + 1e-5f) * wv[d * KC + c]; }
        g_wqkv[i] = w;
    }
    if (i < KC * KC) {
        int d = i / KC;
        g_wpf[i] = pbn[d] * rsqrtf(pbn[3*KC + d] + 1e-5f) * pw[i];
    }
    if (i < 3 * KC) {
        float bvv;
        if (i < KC) bvv = 0.f;
        else if (i < 2 * KC) { int d = i - KC;     float inv = kbn[d] * rsqrtf(kbn[3*KC+d] + 1e-5f); bvv = kbn[KC + d] - inv * kbn[2*KC + d]; }
        else                 { int d = i - 2 * KC; float inv = vbn[d] * rsqrtf(vbn[3*KC+d] + 1e-5f); bvv = vbn[KC + d] - inv * vbn[2*KC + d]; }
        g_bqkv[i] = bvv;
    }
    if (i < KC) {
        float inv = pbn[i] * rsqrtf(pbn[3*KC + i] + 1e-5f);
        g_bp[i] = pbn[KC + i] + inv * (pb[i] - pbn[2*KC + i]);
    }
    if (i < KD * KD) {
        int e = i / KD, d = i % KD;
        float inv = dbn[e] * rsqrtf(dbn[3*KD + e] + 1e-5f);
        float wf = inv * dstw[i];
        g_dw[i] = wf;
        g_dwT[d * KD + e] = wf;
    }
    if (i < KD) {
        float inv = dbn[i] * rsqrtf(dbn[3*KD + i] + 1e-5f);
        g_db[i] = dbn[KD + i] - inv * dbn[2*KD + i];
    }
}

// ---------------- LIF kernels ----------------
__global__ void lif_in(const float* __restrict__ x)
{
    int i = blockIdx.x * blockDim.x + threadIdx.x;
    if (i >= SZ_XT) return;
    int c = i >> 12, j = i & 4095, b = j >> 8, n = j & 255;
    const float* xp = x + ((long long)b * KC + c) * KN + n;
    int8_t* o = g_xs8 + (long long)c * COLS + j;
    float v = 0.f;
#pragma unroll
    for (int t = 0; t < KT; t++) {
        float xv = xp[(long long)t * KB * KC * KN];
        v += (xv - v) * 0.5f;
        float s = (v >= 1.f) ? 1.f : 0.f;
        o[t * TCOL] = (int8_t)s;
        v *= (1.f - s);
    }
}

__global__ void lif_qkv()
{
    int i = blockIdx.x * blockDim.x + threadIdx.x;
    if (i >= 3 * SZ_XT) return;
    int region = i / SZ_XT;
    int il = i - region * SZ_XT;
    float vth = (region == 0) ? 0.05f : 1.0f;
    float* buf = g_qkv + (long long)region * SZ_X;
    long long o = ((long long)(il >> 12)) * COLS + (il & 4095);
    float v = 0.f;
#pragma unroll
    for (int t = 0; t < KT; t++) {
        long long a = o + t * TCOL;
        float xv = buf[a];
        v += (xv - v) * 0.5f;
        float s = (v >= vth) ? 1.f : 0.f;
        buf[a] = s;
        v *= (1.f - s);
    }
}

// ---------------- TIM ----------------
__global__ void tim_init()
{
    int i = blockIdx.x * blockDim.x + threadIdx.x;
    if (i >= SZ_XT) return;
    int c = i >> 12, j = i & 4095;
    float q = g_qkv[(long long)c * COLS + j];
    g_z8[i] = (int8_t)(int)(5.f * q);
}

__global__ void tim_update(int ti, const float* __restrict__ timb)
{
    int i = blockIdx.x * blockDim.x + threadIdx.x;
    if (i >= SZ_XT) return;
    int c = i >> 12, j = i & 4095;
    float cv = 0.2f * g_cb[i] + timb[c];
    float s = (cv * 0.5f >= 0.3f) ? 1.f : 0.f;
    long long qa = (long long)c * COLS + ti * TCOL + j;
    float q = g_qkv[qa];
    float xt = s * 0.6f + q * 0.4f;
    g_qkv[qa] = xt;
    g_z8[i] = (int8_t)(int)(3.f * s + 2.f * q);
}

__global__ void tim_final()
{
    int i = blockIdx.x * blockDim.x + threadIdx.x;
    int cnt = 0;
    if (i < SZ_XT) {
        int c = i >> 12, j = i & 4095;
        float* q = g_qkv + (long long)c * COLS + j;
        float v = 0.f;
#pragma unroll
        for (int t = 0; t < KT; t++) {
            float xv = q[t * TCOL];
            v += (xv - v) * 0.5f;
            float s = (v >= 0.5f) ? 1.f : 0.f;
            q[t * TCOL] = s;
            cnt += (int)s;
            v *= (1.f - s);
        }
    }
#pragma unroll
    for (int o = 16; o > 0; o >>= 1) cnt += __shfl_down_sync(0xffffffffu, cnt, o);
    if ((threadIdx.x & 31) == 0 && cnt) atomicAdd(&g_cnt[0], (float)cnt);
}

__global__ void c1_kernel()
{
    float mean = g_cnt[0] / 6291456.0f;
    g_c1[0] = fminf(1.0f / sqrtf(mean * 48.0f + 1e-6f), 10.0f);
}

// ---------------- dst conv (48x48): ktT3 [z][m][sp*48+e], vtT3 [z][d][sp*256+m] ----------------
__global__ void kt_gemm()
{
    int z = blockIdx.x;
    int h = z >> 6, t = (z >> 4) & 3, b = z & 15;
    int m = threadIdx.x;
    __shared__ float A[KD * KD];
    __shared__ float bs[KD];
    for (int idx = m; idx < KD * KD; idx += 256) A[idx] = g_dw[idx];
    if (m < KD) bs[m] = g_db[m];
    __syncthreads();
    const float* kp = g_qkv + SZ_X + (long long)(h * KD) * COLS + t * TCOL + b * KN + m;
    float kd[KD];
#pragma unroll
    for (int d = 0; d < KD; d++) kd[d] = kp[(long long)d * COLS];
    float s[KD];
#pragma unroll
    for (int e = 0; e < KD; e++) {
        float acc = bs[e];
#pragma unroll
        for (int d = 0; d < KD; d++) acc = fmaf(A[e * KD + d], kd[d], acc);
        s[e] = acc;
    }
    uint2* dst = (uint2*)(g_kt3 + (long long)z * (256 * 144) + m * 144);
#pragma unroll
    for (int sp = 0; sp < 3; sp++) {
#pragma unroll
        for (int w = 0; w < 12; w++) {
            __nv_bfloat16 t0 = __float2bfloat16(s[w*4+0]); s[w*4+0] -= __bfloat162float(t0);
            __nv_bfloat16 t1 = __float2bfloat16(s[w*4+1]); s[w*4+1] -= __bfloat162float(t1);
            __nv_bfloat16 t2 = __float2bfloat16(s[w*4+2]); s[w*4+2] -= __bfloat162float(t2);
            __nv_bfloat16 t3 = __float2bfloat16(s[w*4+3]); s[w*4+3] -= __bfloat162float(t3);
            __nv_bfloat162 p01 = __halves2bfloat162(t0, t1);
            __nv_bfloat162 p23 = __halves2bfloat162(t2, t3);
            uint2 u;
            u.x = *reinterpret_cast<uint32_t*>(&p01);
            u.y = *reinterpret_cast<uint32_t*>(&p23);
            dst[sp * 12 + w] = u;
        }
    }
}

__global__ void vt_gemm()
{
    int z = blockIdx.x;
    int h = z >> 6, t = (z >> 4) & 3, b = z & 15;
    int m = threadIdx.x;
    __shared__ float BT[KD * KD];
    __shared__ float bs[KD];
    for (int idx = m; idx < KD * KD; idx += 256) BT[idx] = g_dwT[idx];
    if (m < KD) bs[m] = g_db[m];
    __syncthreads();
    const float* vp = g_qkv + 2 * SZ_X + (long long)(h * KD) * COLS + t * TCOL + b * KN + m;
    float r[KD];
#pragma unroll
    for (int d = 0; d < KD; d++) r[d] = vp[(long long)d * COLS];
    __nv_bfloat16* Cp = g_vt3 + (long long)z * (48 * 768) + m;
#pragma unroll
    for (int e = 0; e < KD; e++) {
        float s = bs[e];
#pragma unroll
        for (int d = 0; d < KD; d++) s = fmaf(r[d], BT[d * KD + e], s);
        __nv_bfloat16 hh = __float2bfloat16(s); s -= __bfloat162float(hh);
        __nv_bfloat16 mm = __float2bfloat16(s); s -= __bfloat162float(mm);
        __nv_bfloat16 ll = __float2bfloat16(s);
        Cp[e * 768]       = hh;
        Cp[e * 768 + 256] = mm;
        Cp[e * 768 + 512] = ll;
    }
}

// ---------------- misc transforms ----------------
__global__ void make_qhT()
{
    int i = blockIdx.x * blockDim.x + threadIdx.x;
    if (i >= SZ_X) return;
    int n = i & 255;
    int d = (i >> 8) % KD;
    int z = i / (KD * KN);
    int h = z >> 6, t = (z >> 4) & 3, b = z & 15;
    float q = g_qkv[(long long)(h * KD + d) * COLS + t * TCOL + b * KN + n];
    g_qhT[i] = __float2bfloat16(q);
}

__global__ void make_vh(float* __restrict__ outv)
{
    int i = blockIdx.x * blockDim.x + threadIdx.x;
    if (i >= SZ_X) return;
    int c = i >> 14, j = i & 16383;
    int t = j >> 12, b = (j >> 8) & 15, n = j & 255;
    int h = c / KD, d = c - h * KD;
    outv[(((long long)(t * KB + b) * KH + h) * KN + n) * KD + d] = g_qkv[2 * SZ_X + i];
}

__global__ void final_lif(float* __restrict__ out)
{
    int i = blockIdx.x * blockDim.x + threadIdx.x;
    if (i >= SZ_XT) return;
    int c = i >> 12, j = i & 4095, b = j >> 8, n = j & 255;
    const float* p = g_p + (long long)c * COLS + j;
    float* o = out + ((long long)b * KC + c) * KN + n;
    float v = 0.f;
#pragma unroll
    for (int t = 0; t < KT; t++) {
        float xv = p[t * TCOL];
        v += (xv - v) * 0.5f;
        float s = (v >= 1.f) ? 1.f : 0.f;
        o[(long long)t * KB * KC * KN] = s;
        v *= (1.f - s);
    }
}

// ---------------- fused attn-score GEMM + LIF (R8 proven) ----------------
__global__ void __launch_bounds__(256, 2)
attn_lif_fused()
{
    constexpr int BM = 64, BN = 64;
    constexpr int NF = 4;
    __shared__ __align__(16) __nv_bfloat16 As[2][BM][16 + 8];
    __shared__ __align__(16) __nv_bfloat16 Bs[2][16][BN + 8];
    const int tid = threadIdx.x, wid = tid >> 5, lane = tid & 31;
    const int wm = (wid >> 1) * 16, wn = (wid & 1) * 32;
    const int row0 = blockIdx.y * BM, col0 = blockIdx.x * BN;
    const int hb = blockIdx.z, h = hb >> 4, b = hb & 15;

    float acc[4][NF][4];
#pragma unroll
    for (int t = 0; t < 4; t++)
#pragma unroll
        for (int j = 0; j < NF; j++)
#pragma unroll
            for (int q = 0; q < 4; q++) acc[t][j][q] = 0.f;

    for (int t = 0; t < 4; t++) {
        const int z = h * 64 + t * 16 + b;
        const __nv_bfloat16* A = g_kt3 + (long long)z * (256 * 144);
        const __nv_bfloat16* B = g_qhT + (long long)z * (48 * 256);
        uint4 rv;
        auto ldg = [&](int kt) {
            if (tid < 128) {
                int r = tid >> 1, c8 = tid & 1;
                rv = *(const uint4*)&A[(long long)(row0 + r) * 144 + kt * 16 + c8 * 8];
            } else {
                int u = tid & 127;
                int r = u >> 3, c8 = u & 7;
                rv = *(const uint4*)&B[(long long)((kt % 3) * 16 + r) * 256 + col0 + c8 * 8];
            }
        };
        auto sts = [&](int buf) {
            if (tid < 128) { int r = tid >> 1, c8 = tid & 1; *(uint4*)&As[buf][r][c8 * 8] = rv; }
            else { int u = tid & 127; int r = u >> 3, c8 = u & 7; *(uint4*)&Bs[buf][r][c8 * 8] = rv; }
        };
        auto comp = [&](int buf) {
            uint32_t af[4], bf[NF][2];
            {
                int row = wm + (lane & 15);
                int col = (lane >> 4) * 8;
                uint32_t ad = (uint32_t)__cvta_generic_to_shared(&As[buf][row][col]);
                ldm_x4(af[0], af[1], af[2], af[3], ad);
            }
#pragma unroll
            for (int nj = 0; nj < NF; nj++) {
                int r = lane & 15, c = wn + nj * 8;
                uint32_t ad = (uint32_t)__cvta_generic_to_shared(&Bs[buf][r][c]);
                ldm_x2t(bf[nj][0], bf[nj][1], ad);
            }
#pragma unroll
            for (int nj = 0; nj < NF; nj++)
                mma_bf16(acc[t][nj], af, bf[nj]);
        };
        ldg(0); sts(0); __syncthreads();
        int buf = 0;
        for (int kt = 1; kt < 9; kt++) {
            ldg(kt);
            comp(buf);
            sts(buf ^ 1);
            __syncthreads();
            buf ^= 1;
        }
        comp(buf);
        __syncthreads();
    }

    const float c1v = g_c1[0];
    const int m0 = row0 + wm + (lane >> 2);
#pragma unroll
    for (int nj = 0; nj < NF; nj++) {
        int n0 = col0 + wn + nj * 8 + (lane & 3) * 2;
#pragma unroll
        for (int p = 0; p < 2; p++) {
            float v0 = 0.f, v1 = 0.f;
#pragma unroll
            for (int t = 0; t < 4; t++) {
                float x0 = acc[t][nj][p * 2 + 0] * c1v;
                float x1 = acc[t][nj][p * 2 + 1] * c1v;
                v0 += (x0 - v0) * 0.5f;
                v1 += (x1 - v1) * 0.5f;
                float s0 = (v0 >= 0.5f) ? 1.f : 0.f;
                float s1 = (v1 >= 0.5f) ? 1.f : 0.f;
                v0 *= (1.f - s0);
                v1 *= (1.f - s1);
                int z = h * 64 + t * 16 + b;
                __nv_bfloat162 pk = __halves2bfloat162(__float2bfloat16(s0), __float2bfloat16(s1));
                *(__nv_bfloat162*)&g_amap[(long long)z * 65536 + (long long)(m0 + p * 8) * 256 + n0] = pk;
            }
        }
    }
}

// ---------------- fused outT GEMM + identity add (R8 proven) ----------------
__global__ void __launch_bounds__(256)
out_fused(const float* __restrict__ x)
{
    constexpr int BM = 48, BN = 256, BK = 32;
    constexpr int MF = 3, NF = 4;
    __shared__ __align__(16) __nv_bfloat16 As[2][BM][BK + 8];
    __shared__ __align__(16) __nv_bfloat16 Bs[2][BK][BN + 8];
    const int tid = threadIdx.x, wid = tid >> 5, lane = tid & 31;
    const int wn = wid * 32;
    const int z = blockIdx.x;
    const int h = z >> 6, t = (z >> 4) & 3, b = z & 15;
    const __nv_bfloat16* A = g_vt3 + (long long)z * (48 * 768);
    const __nv_bfloat16* B = g_amap + (long long)z * 65536;

    uint4 ar, br[4];
    auto ldg = [&](int kt) {
        int ka = kt * BK, kb = (kt % 8) * BK;
        if (tid < 192) { int r = tid >> 2, c8 = tid & 3;
            ar = *(const uint4*)&A[(long long)r * 768 + ka + c8 * 8]; }
#pragma unroll
        for (int u = 0; u < 4; u++) {
            int idx = tid + u * 256;
            int r = idx >> 5, c8 = idx & 31;
            br[u] = *(const uint4*)&B[(long long)(kb + r) * 256 + c8 * 8];
        }
    };
    auto sts = [&](int buf) {
        if (tid < 192) { int r = tid >> 2, c8 = tid & 3; *(uint4*)&As[buf][r][c8 * 8] = ar; }
#pragma unroll
        for (int u = 0; u < 4; u++) {
            int idx = tid + u * 256;
            int r = idx >> 5, c8 = idx & 31;
            *(uint4*)&Bs[buf][r][c8 * 8] = br[u];
        }
    };

    float acc[MF][NF][4];
#pragma unroll
    for (int i = 0; i < MF; i++)
#pragma unroll
        for (int j = 0; j < NF; j++)
#pragma unroll
            for (int q = 0; q < 4; q++) acc[i][j][q] = 0.f;

    auto comp = [&](int buf) {
#pragma unroll
        for (int kk = 0; kk < 2; kk++) {
            uint32_t af[MF][4], bf[NF][2];
#pragma unroll
            for (int mi = 0; mi < MF; mi++) {
                int row = mi * 16 + (lane & 15);
                int col = kk * 16 + (lane >> 4) * 8;
                uint32_t ad = (uint32_t)__cvta_generic_to_shared(&As[buf][row][col]);
                ldm_x4(af[mi][0], af[mi][1], af[mi][2], af[mi][3], ad);
            }
#pragma unroll
            for (int nj = 0; nj < NF; nj++) {
                int r = kk * 16 + (lane & 15), c = wn + nj * 8;
                uint32_t ad = (uint32_t)__cvta_generic_to_shared(&Bs[buf][r][c]);
                ldm_x2t(bf[nj][0], bf[nj][1], ad);
            }
#pragma unroll
            for (int mi = 0; mi < MF; mi++)
#pragma unroll
                for (int nj = 0; nj < NF; nj++)
                    mma_bf16(acc[mi][nj], af[mi], bf[nj]);
        }
    };

    ldg(0); sts(0); __syncthreads();
    int buf = 0;
    for (int kt = 1; kt < 24; kt++) {
        ldg(kt);
        comp(buf);
        sts(buf ^ 1);
        __syncthreads();
        buf ^= 1;
    }
    comp(buf);

#pragma unroll
    for (int mi = 0; mi < MF; mi++) {
        int d0 = mi * 16 + (lane >> 2);
#pragma unroll
        for (int p = 0; p < 2; p++) {
            int d = d0 + p * 8;
            int c = h * 48 + d;
            const float* xr = x + ((long long)(t * 16 + b) * 384 + c) * 256;
            float* orow = g_o + (long long)c * COLS + t * 4096 + b * 256;
#pragma unroll
            for (int nj = 0; nj < NF; nj++) {
                int n = wn + nj * 8 + (lane & 3) * 2;
                float2 xv = *(const float2*)&xr[n];
                float2 v = {acc[mi][nj][p * 2 + 0] + xv.x, acc[mi][nj][p * 2 + 1] + xv.y};
                *(float2*)&orow[n] = v;
            }
        }
    }
}

// ---------------- fp32 GEMM (proj only — exact numerics) ----------------
template<int BM, int BN, int BK, int TM, int TN>
__global__ void __launch_bounds__(256, 2)
gemm_f32(int M, int N, int K,
         const float* __restrict__ A, int lda,
         const float* __restrict__ B, int ldb,
         float* __restrict__ C, int ldc,
         const float* __restrict__ bias)
{
    constexpr int TX = BN / TN, TY = BM / TM, NT = TX * TY;
    constexpr int A4 = BM * BK / 4, B4 = BK * BN / 4;
    constexpr int APT = A4 / NT, BPT = B4 / NT;
    __shared__ __align__(16) float As[2][BK][BM + 4];
    __shared__ __align__(16) float Bs[2][BK][BN];
    const int tx = threadIdx.x, ty = threadIdx.y;
    const int tid = ty * TX + tx;
    const int row0 = blockIdx.y * BM, col0 = blockIdx.x * BN;
    float4 aR[APT], bR[BPT];
    auto ldg = [&](int k0) {
#pragma unroll
        for (int u = 0; u < APT; u++) {
            int idx = tid + u * NT;
            int r = idx / (BK / 4), c4 = idx % (BK / 4);
            aR[u] = *(const float4*)&A[(long long)(row0 + r) * lda + k0 + c4 * 4];
        }
#pragma unroll
        for (int u = 0; u < BPT; u++) {
            int idx = tid + u * NT;
            int kk = idx / (BN / 4), n4 = idx % (BN / 4);
            bR[u] = *(const float4*)&B[(long long)(k0 + kk) * ldb + col0 + n4 * 4];
        }
    };
    auto sts = [&](int buf) {
#pragma unroll
        for (int u = 0; u < APT; u++) {
            int idx = tid + u * NT;
            int r = idx / (BK / 4), c4 = idx % (BK / 4);
            As[buf][c4 * 4 + 0][r] = aR[u].x;
            As[buf][c4 * 4 + 1][r] = aR[u].y;
            As[buf][c4 * 4 + 2][r] = aR[u].z;
            As[buf][c4 * 4 + 3][r] = aR[u].w;
        }
#pragma unroll
        for (int u = 0; u < BPT; u++) {
            int idx = tid + u * NT;
            int kk = idx / (BN / 4), n4 = idx % (BN / 4);
            *(float4*)&Bs[buf][kk][n4 * 4] = bR[u];
        }
    };
    float acc[TM][TN];
#pragma unroll
    for (int i = 0; i < TM; i++)
#pragma unroll
        for (int j = 0; j < TN; j++) acc[i][j] = 0.f;
    auto comp = [&](int buf) {
#pragma unroll
        for (int kk = 0; kk < BK; kk++) {
            float a[TM], b[TN];
#pragma unroll
            for (int i4 = 0; i4 < TM / 4; i4++) {
                float4 v = *(const float4*)&As[buf][kk][ty * TM + i4 * 4];
                a[i4*4+0]=v.x; a[i4*4+1]=v.y; a[i4*4+2]=v.z; a[i4*4+3]=v.w;
            }
#pragma unroll
            for (int j4 = 0; j4 < TN / 4; j4++) {
                float4 v = *(const float4*)&Bs[buf][kk][tx * TN + j4 * 4];
                b[j4*4+0]=v.x; b[j4*4+1]=v.y; b[j4*4+2]=v.z; b[j4*4+3]=v.w;
            }
#pragma unroll
            for (int i = 0; i < TM; i++)
#pragma unroll
                for (int j = 0; j < TN; j++)
                    acc[i][j] = fmaf(a[i], b[j], acc[i][j]);
        }
    };
    ldg(0); sts(0); __syncthreads();
    const int nit = K / BK;
    int buf = 0;
    for (int it = 1; it < nit; it++) {
        ldg(it * BK); comp(buf); sts(buf ^ 1); __syncthreads(); buf ^= 1;
    }
    comp(buf);
#pragma unroll
    for (int i = 0; i < TM; i++) {
        int r = row0 + ty * TM + i;
        float bv = bias ? bias[r] : 0.f;
#pragma unroll
        for (int j4 = 0; j4 < TN / 4; j4++) {
            float4 v;
            v.x = acc[i][j4*4+0] + bv; v.y = acc[i][j4*4+1] + bv;
            v.z = acc[i][j4*4+2] + bv; v.w = acc[i][j4*4+3] + bv;
            *(float4*)&C[(long long)r * ldc + col0 + tx * TN + j4 * 4] = v;
        }
    }
}

// ---------------- host launcher ----------------
extern "C" void kernel_launch(void* const* d_in, const int* in_sizes, int n_in,
                              void* d_out, int out_size)
{
    (void)in_sizes; (void)n_in; (void)out_size;
    const float* x    = (const float*)d_in[0];
    const float* wq   = (const float*)d_in[1];
    const float* wk   = (const float*)d_in[2];
    const float* wv   = (const float*)d_in[3];
    const float* kbn  = (const float*)d_in[4];
    const float* vbn  = (const float*)d_in[5];
    const float* dstw = (const float*)d_in[6];
    const float* dbn  = (const float*)d_in[7];
    const float* pw   = (const float*)d_in[8];
    const float* pb   = (const float*)d_in[9];
    const float* pbn  = (const float*)d_in[10];
    const float* timw = (const float*)d_in[11];
    const float* timb = (const float*)d_in[12];
    float* out   = (float*)d_out;
    float* out_v = out + SZ_X;

    float *pqkv, *pcb, *po, *pp, *pbp, *pbqkv, *pwpf, *psqkv, *pstim, *pwq;
    int8_t *pxs8, *pxsT, *pz8, *pzT, *pw8q, *pw8t;
    cudaGetSymbolAddress((void**)&pqkv,  g_qkv);
    cudaGetSymbolAddress((void**)&pcb,   g_cb);
    cudaGetSymbolAddress((void**)&po,    g_o);
    cudaGetSymbolAddress((void**)&pp,    g_p);
    cudaGetSymbolAddress((void**)&pbp,   g_bp);
    cudaGetSymbolAddress((void**)&pbqkv, g_bqkv);
    cudaGetSymbolAddress((void**)&pwpf,  g_wpf);
    cudaGetSymbolAddress((void**)&psqkv, g_sqkv);
    cudaGetSymbolAddress((void**)&pstim, g_stim);
    cudaGetSymbolAddress((void**)&pxs8,  g_xs8);
    cudaGetSymbolAddress((void**)&pxsT,  g_xsT);
    cudaGetSymbolAddress((void**)&pz8,   g_z8);
    cudaGetSymbolAddress((void**)&pzT,   g_zT);
    cudaGetSymbolAddress((void**)&pw8q,  g_w8q);
    cudaGetSymbolAddress((void**)&pw8t,  g_w8t);
    cudaGetSymbolAddress((void**)&pwq,   g_wqkv);

    const int TB = 256;
    dim3 tthr(32, 8);

    fold_weights<<<(3 * KC * KC + TB - 1) / TB, TB>>>(wq, wk, wv, pw, pb, kbn, vbn, pbn, dstw, dbn);
    rowscale<<<1152, 256>>>(pwq, 384, psqkv);
    rowscale<<<384, 256>>>(timw, 1920, pstim);
    split8_qkv<<<(1152 * 384 + TB - 1) / TB, TB>>>();
    split8_tim<<<(384 * 1920 + TB - 1) / TB, TB>>>(timw);
    lif_in<<<SZ_XT / TB, TB>>>(x);
    transpose8<<<dim3(COLS / 32, KC / 32), tthr>>>(pxs8, pxsT, KC, COLS);

    // fused q|k|v via s8 digit GEMM: M=1152, N=16384, Kd=384
    gemm_s8<0, 1><<<dim3(COLS / 64, 9), 256>>>(384, pw8q, 1536, pxsT, pqkv, COLS, psqkv, pbqkv);

    lif_qkv<<<3 * SZ_XT / TB, TB>>>();

    // TIM: sequential over t = 1..3, conv via s8 digit GEMM (shifted-B mode)
    tim_init<<<SZ_XT / TB, TB>>>();
    for (int ti = 1; ti < KT; ti++) {
        transpose8<<<dim3(TCOL / 32, KC / 32), tthr>>>(pz8, pzT, KC, TCOL);
        gemm_s8<1, 0><<<dim3(TCOL / 64, 3), 256>>>(1920, pw8t, 7680, pzT, pcb, TCOL, pstim, nullptr);
        tim_update<<<SZ_XT / TB, TB>>>(ti, timb);
    }
    tim_final<<<SZ_XT / TB, TB>>>();
    c1_kernel<<<1, 1>>>();

    // dst conv + shared BN (z = h*64 + t*16 + b)
    kt_gemm<<<512, 256>>>();
    vt_gemm<<<512, 256>>>();
    make_qhT<<<SZ_X / TB, TB>>>();
    make_vh<<<SZ_X / TB, TB>>>(out_v);

    // fused attn scores + LIF (R8 proven)
    attn_lif_fused<<<dim3(4, 4, 128), 256>>>();

    // fused outT GEMM + identity add -> g_o
    out_fused<<<512, 256>>>(x);

    // proj (exact fp32 FFMA): 384 x 16384 x 384
    gemm_f32<128,128,16,8,8><<<dim3(128, 3, 1), dim3(16, 16)>>>(
        KC, COLS, KC, pwpf, KC, po, COLS, pp, COLS, pbp);

    final_lif<<<SZ_XT / TB, TB>>>(out);
}

// round 14
// speedup vs baseline: 1.5472x; 1.5472x over previous
#include <cuda_runtime.h>
#include <cuda_bf16.h>
#include <cstdint>

// ---------------- problem constants ----------------
constexpr int KT = 4, KB = 16, KC = 384, KN = 256, KH = 8, KD = 48;
constexpr int COLS = KT * KB * KN;     // 16384
constexpr int TCOL = KB * KN;          // 4096
constexpr int SZ_XT = KC * TCOL;       // 1,572,864
constexpr int SZ_X  = KC * COLS;       // 6,291,456
constexpr long long SZ_ATT = (long long)KT * KB * KH * KN * KN;   // 33,554,432
constexpr int SZ_COL = KC * 5 * TCOL;  // 7,864,320

// ---------------- device scratch ----------------
__device__ __align__(16) float g_qkv[3 * SZ_X];     // q|k|v fp32, blocked [c][t*4096+b*256+n]
__device__ __align__(16) float g_cb [SZ_XT];        // tim conv out
__device__ __align__(16) float g_o  [SZ_X];         // out + identity, blocked fp32
__device__ __align__(16) float g_p  [SZ_X];         // proj pre-act [c][16384]

__device__ __align__(16) __nv_bfloat16 g_xsb [SZ_X];          // shortcut spikes bf16 [c][16384]
__device__ __align__(16) __nv_bfloat16 g_zt  [SZ_XT];         // tim z-state bf16 [c][4096]
__device__ __align__(16) __nv_bfloat16 g_colb[SZ_COL];        // im2col bf16
__device__ __align__(16) __nv_bfloat16 g_qhT [SZ_X];          // q heads bf16 [z][d][n]
__device__ __align__(16) __nv_bfloat16 g_amap[SZ_ATT];        // attn map bf16 [z][m][n]
__device__ __align__(16) __nv_bfloat16 g_wqkv3[1152 * 1152];  // qkv weights 3-split along K
__device__ __align__(16) __nv_bfloat16 g_timw3[384 * 5760];
__device__ __align__(16) __nv_bfloat16 g_kt3[512 * 256 * 144];   // [z][m][sp*48+e]
__device__ __align__(16) __nv_bfloat16 g_vt3[512 * 48 * 768];    // [z][d][sp*256+m]

__device__ __align__(16) float g_wqkv[3 * KC * KC];
__device__ float g_bqkv[3 * KC];
__device__ __align__(16) float g_wpf[KC * KC];
__device__ float g_bp[KC];
__device__ float g_dw[KD * KD], g_dwT[KD * KD], g_db[KD];
__device__ float g_cnt[1], g_c1[1];

// ---------------- mma helpers ----------------
__device__ __forceinline__ void ldm_x4(uint32_t& r0, uint32_t& r1, uint32_t& r2, uint32_t& r3, uint32_t addr)
{
    asm volatile("ldmatrix.sync.aligned.m8n8.x4.shared.b16 {%0,%1,%2,%3}, [%4];"
                 : "=r"(r0), "=r"(r1), "=r"(r2), "=r"(r3) : "r"(addr));
}
__device__ __forceinline__ void ldm_x2t(uint32_t& r0, uint32_t& r1, uint32_t addr)
{
    asm volatile("ldmatrix.sync.aligned.m8n8.x2.trans.shared.b16 {%0,%1}, [%2];"
                 : "=r"(r0), "=r"(r1) : "r"(addr));
}
__device__ __forceinline__ void mma_bf16(float* c, const uint32_t* a, const uint32_t* b)
{
    asm volatile("mma.sync.aligned.m16n8k16.row.col.f32.bf16.bf16.f32 "
                 "{%0,%1,%2,%3}, {%4,%5,%6,%7}, {%8,%9}, {%0,%1,%2,%3};"
                 : "+f"(c[0]), "+f"(c[1]), "+f"(c[2]), "+f"(c[3])
                 : "r"(a[0]), "r"(a[1]), "r"(a[2]), "r"(a[3]), "r"(b[0]), "r"(b[1]));
}

// ---------------- bf16 tensor GEMM (R3/R8 register-staged double-buffer core) ----------------
template<int BM, int BN, int BK, int WM, int WN, int CYCA, int CYCB, int HASB, int OCC>
__global__ void __launch_bounds__(256, OCC)
gemm_bf16(int KTOT,
          const __nv_bfloat16* __restrict__ A, int lda, long long sA,
          const __nv_bfloat16* __restrict__ B, int ldb, long long sB,
          float* __restrict__ C, int ldc, long long sC,
          const float* __restrict__ bias)
{
    constexpr int NWM = BM / WM, NWN = BN / WN;
    constexpr int NW = NWM * NWN;
    static_assert(NW == 8, "8 warps");
    constexpr int NT = NW * 32;
    constexpr int MF = WM / 16, NF = WN / 8, KK = BK / 16;
    constexpr int APAD = 8, BPAD = 8;
    __shared__ __align__(16) __nv_bfloat16 As[2][BM][BK + APAD];
    __shared__ __align__(16) __nv_bfloat16 Bs[2][BK][BN + BPAD];

    const int tid = threadIdx.x;
    const int wid = tid >> 5, lane = tid & 31;
    const int wm = (wid / NWN) * WM, wn = (wid % NWN) * WN;
    const int row0 = blockIdx.y * BM, col0 = blockIdx.x * BN;
    const int z = blockIdx.z;
    A += (long long)z * sA;
    B += (long long)z * sB;
    C += (long long)z * sC;

    constexpr int A4 = BM * BK / 8, B4 = BK * BN / 8;
    constexpr int APT = (A4 + NT - 1) / NT, BPT = (B4 + NT - 1) / NT;
    uint4 ar[APT], br[BPT];
    const int ktiles = KTOT / BK;

    auto ldg = [&](int kt) {
        int ka = CYCA ? (kt % (CYCA / BK)) * BK : kt * BK;
        int kb = CYCB ? (kt % (CYCB / BK)) * BK : kt * BK;
#pragma unroll
        for (int u = 0; u < APT; u++) {
            int idx = tid + u * NT;
            if (A4 % NT == 0 || idx < A4) {
                int r = idx / (BK / 8), c8 = idx % (BK / 8);
                ar[u] = *(const uint4*)&A[(long long)(row0 + r) * lda + ka + c8 * 8];
            }
        }
#pragma unroll
        for (int u = 0; u < BPT; u++) {
            int idx = tid + u * NT;
            if (B4 % NT == 0 || idx < B4) {
                int r = idx / (BN / 8), c8 = idx % (BN / 8);
                br[u] = *(const uint4*)&B[(long long)(kb + r) * ldb + col0 + c8 * 8];
            }
        }
    };
    auto sts = [&](int buf) {
#pragma unroll
        for (int u = 0; u < APT; u++) {
            int idx = tid + u * NT;
            if (A4 % NT == 0 || idx < A4) {
                int r = idx / (BK / 8), c8 = idx % (BK / 8);
                *(uint4*)&As[buf][r][c8 * 8] = ar[u];
            }
        }
#pragma unroll
        for (int u = 0; u < BPT; u++) {
            int idx = tid + u * NT;
            if (B4 % NT == 0 || idx < B4) {
                int r = idx / (BN / 8), c8 = idx % (BN / 8);
                *(uint4*)&Bs[buf][r][c8 * 8] = br[u];
            }
        }
    };

    float acc[MF][NF][4];
#pragma unroll
    for (int i = 0; i < MF; i++)
#pragma unroll
        for (int j = 0; j < NF; j++)
#pragma unroll
            for (int q = 0; q < 4; q++) acc[i][j][q] = 0.f;

    auto comp = [&](int buf) {
#pragma unroll
        for (int kk = 0; kk < KK; kk++) {
            uint32_t af[MF][4], bf[NF][2];
#pragma unroll
            for (int mi = 0; mi < MF; mi++) {
                int row = wm + mi * 16 + (lane & 15);
                int col = kk * 16 + (lane >> 4) * 8;
                uint32_t ad = (uint32_t)__cvta_generic_to_shared(&As[buf][row][col]);
                ldm_x4(af[mi][0], af[mi][1], af[mi][2], af[mi][3], ad);
            }
#pragma unroll
            for (int nj = 0; nj < NF; nj++) {
                int r = kk * 16 + (lane & 15);
                int c = wn + nj * 8;
                uint32_t ad = (uint32_t)__cvta_generic_to_shared(&Bs[buf][r][c]);
                ldm_x2t(bf[nj][0], bf[nj][1], ad);
            }
#pragma unroll
            for (int mi = 0; mi < MF; mi++)
#pragma unroll
                for (int nj = 0; nj < NF; nj++)
                    mma_bf16(acc[mi][nj], af[mi], bf[nj]);
        }
    };

    ldg(0); sts(0); __syncthreads();
    int buf = 0;
    for (int kt = 1; kt < ktiles; kt++) {
        ldg(kt);
        comp(buf);
        sts(buf ^ 1);
        __syncthreads();
        buf ^= 1;
    }
    comp(buf);

#pragma unroll
    for (int mi = 0; mi < MF; mi++) {
        int r0 = row0 + wm + mi * 16 + (lane >> 2);
        float b0 = HASB ? bias[r0] : 0.f;
        float b1 = HASB ? bias[r0 + 8] : 0.f;
#pragma unroll
        for (int nj = 0; nj < NF; nj++) {
            int c0 = col0 + wn + nj * 8 + (lane & 3) * 2;
            float2 v0 = {acc[mi][nj][0] + b0, acc[mi][nj][1] + b0};
            float2 v1 = {acc[mi][nj][2] + b1, acc[mi][nj][3] + b1};
            *(float2*)&C[(long long)r0 * ldc + c0] = v0;
            *(float2*)&C[(long long)(r0 + 8) * ldc + c0] = v1;
        }
    }
}

// ---------------- fused attn-score GEMM + LIF (R8 proven) ----------------
__global__ void __launch_bounds__(256, 2)
attn_lif_fused()
{
    constexpr int BM = 64, BN = 64, BK = 16;
    constexpr int NF = 4;
    __shared__ __align__(16) __nv_bfloat16 As[2][BM][BK + 8];
    __shared__ __align__(16) __nv_bfloat16 Bs[2][BK][BN + 8];
    const int tid = threadIdx.x, wid = tid >> 5, lane = tid & 31;
    const int wm = (wid >> 1) * 16, wn = (wid & 1) * 32;
    const int row0 = blockIdx.y * BM, col0 = blockIdx.x * BN;
    const int hb = blockIdx.z, h = hb >> 4, b = hb & 15;

    float acc[4][NF][4];
#pragma unroll
    for (int t = 0; t < 4; t++)
#pragma unroll
        for (int j = 0; j < NF; j++)
#pragma unroll
            for (int q = 0; q < 4; q++) acc[t][j][q] = 0.f;

    for (int t = 0; t < 4; t++) {
        const int z = h * 64 + t * 16 + b;
        const __nv_bfloat16* A = g_kt3 + (long long)z * (256 * 144);
        const __nv_bfloat16* B = g_qhT + (long long)z * (48 * 256);
        uint4 rv;
        auto ldg = [&](int kt) {
            if (tid < 128) {
                int r = tid >> 1, c8 = tid & 1;
                rv = *(const uint4*)&A[(long long)(row0 + r) * 144 + kt * 16 + c8 * 8];
            } else {
                int u = tid & 127;
                int r = u >> 3, c8 = u & 7;
                rv = *(const uint4*)&B[(long long)((kt % 3) * 16 + r) * 256 + col0 + c8 * 8];
            }
        };
        auto sts = [&](int buf) {
            if (tid < 128) { int r = tid >> 1, c8 = tid & 1; *(uint4*)&As[buf][r][c8 * 8] = rv; }
            else { int u = tid & 127; int r = u >> 3, c8 = u & 7; *(uint4*)&Bs[buf][r][c8 * 8] = rv; }
        };
        auto comp = [&](int buf) {
            uint32_t af[4], bf[NF][2];
            {
                int row = wm + (lane & 15);
                int col = (lane >> 4) * 8;
                uint32_t ad = (uint32_t)__cvta_generic_to_shared(&As[buf][row][col]);
                ldm_x4(af[0], af[1], af[2], af[3], ad);
            }
#pragma unroll
            for (int nj = 0; nj < NF; nj++) {
                int r = lane & 15, c = wn + nj * 8;
                uint32_t ad = (uint32_t)__cvta_generic_to_shared(&Bs[buf][r][c]);
                ldm_x2t(bf[nj][0], bf[nj][1], ad);
            }
#pragma unroll
            for (int nj = 0; nj < NF; nj++)
                mma_bf16(acc[t][nj], af, bf[nj]);
        };
        ldg(0); sts(0); __syncthreads();
        int buf = 0;
        for (int kt = 1; kt < 9; kt++) {
            ldg(kt);
            comp(buf);
            sts(buf ^ 1);
            __syncthreads();
            buf ^= 1;
        }
        comp(buf);
        __syncthreads();
    }

    const float c1v = g_c1[0];
    const int m0 = row0 + wm + (lane >> 2);
#pragma unroll
    for (int nj = 0; nj < NF; nj++) {
        int n0 = col0 + wn + nj * 8 + (lane & 3) * 2;
#pragma unroll
        for (int p = 0; p < 2; p++) {
            float v0 = 0.f, v1 = 0.f;
#pragma unroll
            for (int t = 0; t < 4; t++) {
                float x0 = acc[t][nj][p * 2 + 0] * c1v;
                float x1 = acc[t][nj][p * 2 + 1] * c1v;
                v0 += (x0 - v0) * 0.5f;
                v1 += (x1 - v1) * 0.5f;
                float s0 = (v0 >= 0.5f) ? 1.f : 0.f;
                float s1 = (v1 >= 0.5f) ? 1.f : 0.f;
                v0 *= (1.f - s0);
                v1 *= (1.f - s1);
                int z = h * 64 + t * 16 + b;
                __nv_bfloat162 pk = __halves2bfloat162(__float2bfloat16(s0), __float2bfloat16(s1));
                *(__nv_bfloat162*)&g_amap[(long long)z * 65536 + (long long)(m0 + p * 8) * 256 + n0] = pk;
            }
        }
    }
}

// ---------------- fused outT GEMM + identity add (R8 proven) ----------------
__global__ void __launch_bounds__(256)
out_fused(const float* __restrict__ x)
{
    constexpr int BM = 48, BN = 256, BK = 32;
    constexpr int MF = 3, NF = 4;
    __shared__ __align__(16) __nv_bfloat16 As[2][BM][BK + 8];
    __shared__ __align__(16) __nv_bfloat16 Bs[2][BK][BN + 8];
    const int tid = threadIdx.x, wid = tid >> 5, lane = tid & 31;
    const int wn = wid * 32;
    const int z = blockIdx.x;
    const int h = z >> 6, t = (z >> 4) & 3, b = z & 15;
    const __nv_bfloat16* A = g_vt3 + (long long)z * (48 * 768);
    const __nv_bfloat16* B = g_amap + (long long)z * 65536;

    uint4 ar, br[4];
    auto ldg = [&](int kt) {
        int ka = kt * BK, kb = (kt % 8) * BK;
        if (tid < 192) { int r = tid >> 2, c8 = tid & 3;
            ar = *(const uint4*)&A[(long long)r * 768 + ka + c8 * 8]; }
#pragma unroll
        for (int u = 0; u < 4; u++) {
            int idx = tid + u * 256;
            int r = idx >> 5, c8 = idx & 31;
            br[u] = *(const uint4*)&B[(long long)(kb + r) * 256 + c8 * 8];
        }
    };
    auto sts = [&](int buf) {
        if (tid < 192) { int r = tid >> 2, c8 = tid & 3; *(uint4*)&As[buf][r][c8 * 8] = ar; }
#pragma unroll
        for (int u = 0; u < 4; u++) {
            int idx = tid + u * 256;
            int r = idx >> 5, c8 = idx & 31;
            *(uint4*)&Bs[buf][r][c8 * 8] = br[u];
        }
    };

    float acc[MF][NF][4];
#pragma unroll
    for (int i = 0; i < MF; i++)
#pragma unroll
        for (int j = 0; j < NF; j++)
#pragma unroll
            for (int q = 0; q < 4; q++) acc[i][j][q] = 0.f;

    auto comp = [&](int buf) {
#pragma unroll
        for (int kk = 0; kk < 2; kk++) {
            uint32_t af[MF][4], bf[NF][2];
#pragma unroll
            for (int mi = 0; mi < MF; mi++) {
                int row = mi * 16 + (lane & 15);
                int col = kk * 16 + (lane >> 4) * 8;
                uint32_t ad = (uint32_t)__cvta_generic_to_shared(&As[buf][row][col]);
                ldm_x4(af[mi][0], af[mi][1], af[mi][2], af[mi][3], ad);
            }
#pragma unroll
            for (int nj = 0; nj < NF; nj++) {
                int r = kk * 16 + (lane & 15), c = wn + nj * 8;
                uint32_t ad = (uint32_t)__cvta_generic_to_shared(&Bs[buf][r][c]);
                ldm_x2t(bf[nj][0], bf[nj][1], ad);
            }
#pragma unroll
            for (int mi = 0; mi < MF; mi++)
#pragma unroll
                for (int nj = 0; nj < NF; nj++)
                    mma_bf16(acc[mi][nj], af[mi], bf[nj]);
        }
    };

    ldg(0); sts(0); __syncthreads();
    int buf = 0;
    for (int kt = 1; kt < 24; kt++) {
        ldg(kt);
        comp(buf);
        sts(buf ^ 1);
        __syncthreads();
        buf ^= 1;
    }
    comp(buf);

#pragma unroll
    for (int mi = 0; mi < MF; mi++) {
        int d0 = mi * 16 + (lane >> 2);
#pragma unroll
        for (int p = 0; p < 2; p++) {
            int d = d0 + p * 8;
            int c = h * 48 + d;
            const float* xr = x + ((long long)(t * 16 + b) * 384 + c) * 256;
            float* orow = g_o + (long long)c * COLS + t * 4096 + b * 256;
#pragma unroll
            for (int nj = 0; nj < NF; nj++) {
                int n = wn + nj * 8 + (lane & 3) * 2;
                float2 xv = *(const float2*)&xr[n];
                float2 v = {acc[mi][nj][p * 2 + 0] + xv.x, acc[mi][nj][p * 2 + 1] + xv.y};
                *(float2*)&orow[n] = v;
            }
        }
    }
}

// ---------------- fp32 GEMM (proj only — exact numerics) ----------------
template<int BM, int BN, int BK, int TM, int TN>
__global__ void __launch_bounds__(256, 2)
gemm_f32(int M, int N, int K,
         const float* __restrict__ A, int lda,
         const float* __restrict__ B, int ldb,
         float* __restrict__ C, int ldc,
         const float* __restrict__ bias)
{
    constexpr int TX = BN / TN, TY = BM / TM, NT = TX * TY;
    constexpr int A4 = BM * BK / 4, B4 = BK * BN / 4;
    constexpr int APT = A4 / NT, BPT = B4 / NT;
    __shared__ __align__(16) float As[2][BK][BM + 4];
    __shared__ __align__(16) float Bs[2][BK][BN];
    const int tx = threadIdx.x, ty = threadIdx.y;
    const int tid = ty * TX + tx;
    const int row0 = blockIdx.y * BM, col0 = blockIdx.x * BN;
    float4 aR[APT], bR[BPT];
    auto ldg = [&](int k0) {
#pragma unroll
        for (int u = 0; u < APT; u++) {
            int idx = tid + u * NT;
            int r = idx / (BK / 4), c4 = idx % (BK / 4);
            aR[u] = *(const float4*)&A[(long long)(row0 + r) * lda + k0 + c4 * 4];
        }
#pragma unroll
        for (int u = 0; u < BPT; u++) {
            int idx = tid + u * NT;
            int kk = idx / (BN / 4), n4 = idx % (BN / 4);
            bR[u] = *(const float4*)&B[(long long)(k0 + kk) * ldb + col0 + n4 * 4];
        }
    };
    auto sts = [&](int buf) {
#pragma unroll
        for (int u = 0; u < APT; u++) {
            int idx = tid + u * NT;
            int r = idx / (BK / 4), c4 = idx % (BK / 4);
            As[buf][c4 * 4 + 0][r] = aR[u].x;
            As[buf][c4 * 4 + 1][r] = aR[u].y;
            As[buf][c4 * 4 + 2][r] = aR[u].z;
            As[buf][c4 * 4 + 3][r] = aR[u].w;
        }
#pragma unroll
        for (int u = 0; u < BPT; u++) {
            int idx = tid + u * NT;
            int kk = idx / (BN / 4), n4 = idx % (BN / 4);
            *(float4*)&Bs[buf][kk][n4 * 4] = bR[u];
        }
    };
    float acc[TM][TN];
#pragma unroll
    for (int i = 0; i < TM; i++)
#pragma unroll
        for (int j = 0; j < TN; j++) acc[i][j] = 0.f;
    auto comp = [&](int buf) {
#pragma unroll
        for (int kk = 0; kk < BK; kk++) {
            float a[TM], b[TN];
#pragma unroll
            for (int i4 = 0; i4 < TM / 4; i4++) {
                float4 v = *(const float4*)&As[buf][kk][ty * TM + i4 * 4];
                a[i4*4+0]=v.x; a[i4*4+1]=v.y; a[i4*4+2]=v.z; a[i4*4+3]=v.w;
            }
#pragma unroll
            for (int j4 = 0; j4 < TN / 4; j4++) {
                float4 v = *(const float4*)&Bs[buf][kk][tx * TN + j4 * 4];
                b[j4*4+0]=v.x; b[j4*4+1]=v.y; b[j4*4+2]=v.z; b[j4*4+3]=v.w;
            }
#pragma unroll
            for (int i = 0; i < TM; i++)
#pragma unroll
                for (int j = 0; j < TN; j++)
                    acc[i][j] = fmaf(a[i], b[j], acc[i][j]);
        }
    };
    ldg(0); sts(0); __syncthreads();
    const int nit = K / BK;
    int buf = 0;
    for (int it = 1; it < nit; it++) {
        ldg(it * BK); comp(buf); sts(buf ^ 1); __syncthreads(); buf ^= 1;
    }
    comp(buf);
#pragma unroll
    for (int i = 0; i < TM; i++) {
        int r = row0 + ty * TM + i;
        float bv = bias ? bias[r] : 0.f;
#pragma unroll
        for (int j4 = 0; j4 < TN / 4; j4++) {
            float4 v;
            v.x = acc[i][j4*4+0] + bv; v.y = acc[i][j4*4+1] + bv;
            v.z = acc[i][j4*4+2] + bv; v.w = acc[i][j4*4+3] + bv;
            *(float4*)&C[(long long)r * ldc + col0 + tx * TN + j4 * 4] = v;
        }
    }
}

// ---------------- split helper ----------------
__device__ __forceinline__ void split3f(float x, __nv_bfloat16& h, __nv_bfloat16& m, __nv_bfloat16& l)
{
    __nv_bfloat16 bh = __float2bfloat16(x);
    float r1 = x - __bfloat162float(bh);
    __nv_bfloat16 bm = __float2bfloat16(r1);
    float r2 = r1 - __bfloat162float(bm);
    h = bh; m = bm; l = __float2bfloat16(r2);
}

// ---------------- BN folding ----------------
__global__ void fold_weights(const float* __restrict__ wq, const float* __restrict__ wk,
                             const float* __restrict__ wv, const float* __restrict__ pw,
                             const float* __restrict__ pb, const float* __restrict__ kbn,
                             const float* __restrict__ vbn, const float* __restrict__ pbn,
                             const float* __restrict__ dstw, const float* __restrict__ dbn)
{
    int i = blockIdx.x * blockDim.x + threadIdx.x;
    if (i == 0) g_cnt[0] = 0.f;
    if (i < 3 * KC * KC) {
        int rr = i / KC, c = i % KC;
        float w;
        if (rr < KC) w = wq[rr * KC + c];
        else if (rr < 2 * KC) { int d = rr - KC;     w = kbn[d] * rsqrtf(kbn[3*KC + d] + 1e-5f) * wk[d * KC + c]; }
        else                  { int d = rr - 2 * KC; w = vbn[d] * rsqrtf(vbn[3*KC + d] + 1e-5f) * wv[d * KC + c]; }
        g_wqkv[i] = w;
    }
    if (i < KC * KC) {
        int d = i / KC;
        g_wpf[i] = pbn[d] * rsqrtf(pbn[3*KC + d] + 1e-5f) * pw[i];
    }
    if (i < 3 * KC) {
        float bvv;
        if (i < KC) bvv = 0.f;
        else if (i < 2 * KC) { int d = i - KC;     float inv = kbn[d] * rsqrtf(kbn[3*KC+d] + 1e-5f); bvv = kbn[KC + d] - inv * kbn[2*KC + d]; }
        else                 { int d = i - 2 * KC; float inv = vbn[d] * rsqrtf(vbn[3*KC+d] + 1e-5f); bvv = vbn[KC + d] - inv * vbn[2*KC + d]; }
        g_bqkv[i] = bvv;
    }
    if (i < KC) {
        float inv = pbn[i] * rsqrtf(pbn[3*KC + i] + 1e-5f);
        g_bp[i] = pbn[KC + i] + inv * (pb[i] - pbn[2*KC + i]);
    }
    if (i < KD * KD) {
        int e = i / KD, d = i % KD;
        float inv = dbn[e] * rsqrtf(dbn[3*KD + e] + 1e-5f);
        float wf = inv * dstw[i];
        g_dw[i] = wf;
        g_dwT[d * KD + e] = wf;
    }
    if (i < KD) {
        float inv = dbn[i] * rsqrtf(dbn[3*KD + i] + 1e-5f);
        g_db[i] = dbn[KD + i] - inv * dbn[2*KD + i];
    }
}

__global__ void split_qkv()
{
    int i = blockIdx.x * blockDim.x + threadIdx.x;
    if (i >= 3 * KC * KC) return;
    int r = i / KC, c = i % KC;
    __nv_bfloat16 h, m, l;
    split3f(g_wqkv[i], h, m, l);
    __nv_bfloat16* row = g_wqkv3 + (long long)r * 1152;
    row[c] = h; row[KC + c] = m; row[2 * KC + c] = l;
}

__global__ void split_tim(const float* __restrict__ timw)
{
    int i = blockIdx.x * blockDim.x + threadIdx.x;
    if (i >= KC * KC * 5) return;
    int r = i / (KC * 5), c = i % (KC * 5);
    __nv_bfloat16 h, m, l;
    split3f(timw[i], h, m, l);
    __nv_bfloat16* row = g_timw3 + (long long)r * 5760;
    row[c] = h; row[1920 + c] = m; row[3840 + c] = l;
}

// ---------------- LIF kernels ----------------
__global__ void lif_in(const float* __restrict__ x)
{
    int i = blockIdx.x * blockDim.x + threadIdx.x;
    if (i >= SZ_XT) return;
    int c = i >> 12, j = i & 4095, b = j >> 8, n = j & 255;
    const float* xp = x + ((long long)b * KC + c) * KN + n;
    __nv_bfloat16* o = g_xsb + (long long)c * COLS + j;
    float v = 0.f;
#pragma unroll
    for (int t = 0; t < KT; t++) {
        float xv = xp[(long long)t * KB * KC * KN];
        v += (xv - v) * 0.5f;
        float s = (v >= 1.f) ? 1.f : 0.f;
        o[t * TCOL] = __float2bfloat16(s);
        v *= (1.f - s);
    }
}

// fused LIF over q|k|v; region 0 seeds TIM z-state (t=0), region 2 writes out_v
__global__ void lif_qkv_fused(float* __restrict__ outv)
{
    int i = blockIdx.x * blockDim.x + threadIdx.x;
    if (i >= 3 * SZ_XT) return;
    int region = i / SZ_XT;
    int il = i - region * SZ_XT;
    int c = il >> 12, j = il & 4095;
    float vth = (region == 0) ? 0.05f : 1.0f;
    float* buf = g_qkv + (long long)region * SZ_X;
    long long o = ((long long)c) * COLS + j;
    int b = j >> 8, n = j & 255;
    int h = c / KD, d = c - h * KD;
    float v = 0.f;
#pragma unroll
    for (int t = 0; t < KT; t++) {
        long long a = o + t * TCOL;
        float xv = buf[a];
        v += (xv - v) * 0.5f;
        float s = (v >= vth) ? 1.f : 0.f;
        buf[a] = s;
        v *= (1.f - s);
        if (region == 0 && t == 0)
            g_zt[c * TCOL + j] = __float2bfloat16(5.0f * s);
        if (region == 2)
            outv[(((long long)(t * KB + b) * KH + h) * KN + n) * KD + d] = s;
    }
}

// ---------------- TIM ----------------
__global__ void im2col_k()
{
    int i = blockIdx.x * blockDim.x + threadIdx.x;
    if (i >= SZ_COL) return;
    int j = i & 4095, r = i >> 12;
    int kk = r % 5, ci = r / 5;
    int n = j & 255;
    int n2 = n + kk - 2;
    __nv_bfloat16 v = __float2bfloat16(0.f);
    if (n2 >= 0 && n2 < KN) v = g_zt[ci * TCOL + (j - n) + n2];
    g_colb[i] = v;
}

__global__ void tim_update(int ti, const float* __restrict__ timb)
{
    int i = blockIdx.x * blockDim.x + threadIdx.x;
    if (i >= SZ_XT) return;
    int c = i >> 12, j = i & 4095;
    float cv = 0.2f * g_cb[i] + timb[c];
    float s = (cv * 0.5f >= 0.3f) ? 1.f : 0.f;
    long long qa = (long long)c * COLS + ti * TCOL + j;
    float q = g_qkv[qa];
    float xt = s * 0.6f + q * 0.4f;
    g_qkv[qa] = xt;
    g_zt[i] = __float2bfloat16(3.0f * s + 2.0f * q);
}

__global__ void tim_final()
{
    int i = blockIdx.x * blockDim.x + threadIdx.x;
    int cnt = 0;
    if (i < SZ_XT) {
        int c = i >> 12, j = i & 4095;
        float* q = g_qkv + (long long)c * COLS + j;
        float v = 0.f;
#pragma unroll
        for (int t = 0; t < KT; t++) {
            float xv = q[t * TCOL];
            v += (xv - v) * 0.5f;
            float s = (v >= 0.5f) ? 1.f : 0.f;
            q[t * TCOL] = s;
            cnt += (int)s;
            v *= (1.f - s);
        }
    }
#pragma unroll
    for (int o = 16; o > 0; o >>= 1) cnt += __shfl_down_sync(0xffffffffu, cnt, o);
    if ((threadIdx.x & 31) == 0 && cnt) atomicAdd(&g_cnt[0], (float)cnt);
}

__global__ void c1_kernel()
{
    float mean = g_cnt[0] / 6291456.0f;
    g_c1[0] = fminf(1.0f / sqrtf(mean * 48.0f + 1e-6f), 10.0f);
}

// ---------------- dst conv (48x48): ktT3 [z][m][sp*48+e], vtT3 [z][d][sp*256+m] ----------------
__global__ void kt_gemm()
{
    int z = blockIdx.x;                 // z = h*64 + t*16 + b
    int h = z >> 6, t = (z >> 4) & 3, b = z & 15;
    int m = threadIdx.x;
    __shared__ float A[KD * KD];
    __shared__ float bs[KD];
    for (int idx = m; idx < KD * KD; idx += 256) A[idx] = g_dw[idx];
    if (m < KD) bs[m] = g_db[m];
    __syncthreads();
    const float* kp = g_qkv + SZ_X + (long long)(h * KD) * COLS + t * TCOL + b * KN + m;
    float kd[KD];
#pragma unroll
    for (int d = 0; d < KD; d++) kd[d] = kp[(long long)d * COLS];
    float s[KD];
#pragma unroll
    for (int e = 0; e < KD; e++) {
        float acc = bs[e];
#pragma unroll
        for (int d = 0; d < KD; d++) acc = fmaf(A[e * KD + d], kd[d], acc);
        s[e] = acc;
    }
    uint2* dst = (uint2*)(g_kt3 + (long long)z * (256 * 144) + m * 144);
#pragma unroll
    for (int sp = 0; sp < 3; sp++) {
#pragma unroll
        for (int w = 0; w < 12; w++) {
            __nv_bfloat16 t0 = __float2bfloat16(s[w*4+0]); s[w*4+0] -= __bfloat162float(t0);
            __nv_bfloat16 t1 = __float2bfloat16(s[w*4+1]); s[w*4+1] -= __bfloat162float(t1);
            __nv_bfloat16 t2 = __float2bfloat16(s[w*4+2]); s[w*4+2] -= __bfloat162float(t2);
            __nv_bfloat16 t3 = __float2bfloat16(s[w*4+3]); s[w*4+3] -= __bfloat162float(t3);
            __nv_bfloat162 p01 = __halves2bfloat162(t0, t1);
            __nv_bfloat162 p23 = __halves2bfloat162(t2, t3);
            uint2 u;
            u.x = *reinterpret_cast<uint32_t*>(&p01);
            u.y = *reinterpret_cast<uint32_t*>(&p23);
            dst[sp * 12 + w] = u;
        }
    }
}

__global__ void vt_gemm()
{
    int z = blockIdx.x;
    int h = z >> 6, t = (z >> 4) & 3, b = z & 15;
    int m = threadIdx.x;
    __shared__ float BT[KD * KD];
    __shared__ float bs[KD];
    for (int idx = m; idx < KD * KD; idx += 256) BT[idx] = g_dwT[idx];
    if (m < KD) bs[m] = g_db[m];
    __syncthreads();
    const float* vp = g_qkv + 2 * SZ_X + (long long)(h * KD) * COLS + t * TCOL + b * KN + m;
    float r[KD];
#pragma unroll
    for (int d = 0; d < KD; d++) r[d] = vp[(long long)d * COLS];
    __nv_bfloat16* Cp = g_vt3 + (long long)z * (48 * 768) + m;
#pragma unroll
    for (int e = 0; e < KD; e++) {
        float s = bs[e];
#pragma unroll
        for (int d = 0; d < KD; d++) s = fmaf(r[d], BT[d * KD + e], s);
        __nv_bfloat16 hh = __float2bfloat16(s); s -= __bfloat162float(hh);
        __nv_bfloat16 mm = __float2bfloat16(s); s -= __bfloat162float(mm);
        __nv_bfloat16 ll = __float2bfloat16(s);
        Cp[e * 768]       = hh;
        Cp[e * 768 + 256] = mm;
        Cp[e * 768 + 512] = ll;
    }
}

// ---------------- misc transforms ----------------
__global__ void make_qhT()   // q spikes -> bf16 [z][d][n]
{
    int i = blockIdx.x * blockDim.x + threadIdx.x;
    if (i >= SZ_X) return;
    int n = i & 255;
    int d = (i >> 8) % KD;
    int z = i / (KD * KN);
    int h = z >> 6, t = (z >> 4) & 3, b = z & 15;
    float q = g_qkv[(long long)(h * KD + d) * COLS + t * TCOL + b * KN + n];
    g_qhT[i] = __float2bfloat16(q);
}

__global__ void final_lif(float* __restrict__ out)
{
    int i = blockIdx.x * blockDim.x + threadIdx.x;
    if (i >= SZ_XT) return;
    int c = i >> 12, j = i & 4095, b = j >> 8, n = j & 255;
    const float* p = g_p + (long long)c * COLS + j;
    float* o = out + ((long long)b * KC + c) * KN + n;
    float v = 0.f;
#pragma unroll
    for (int t = 0; t < KT; t++) {
        float xv = p[t * TCOL];
        v += (xv - v) * 0.5f;
        float s = (v >= 1.f) ? 1.f : 0.f;
        o[(long long)t * KB * KC * KN] = s;
        v *= (1.f - s);
    }
}

// ---------------- host launcher ----------------
extern "C" void kernel_launch(void* const* d_in, const int* in_sizes, int n_in,
                              void* d_out, int out_size)
{
    (void)in_sizes; (void)n_in; (void)out_size;
    const float* x    = (const float*)d_in[0];
    const float* wq   = (const float*)d_in[1];
    const float* wk   = (const float*)d_in[2];
    const float* wv   = (const float*)d_in[3];
    const float* kbn  = (const float*)d_in[4];
    const float* vbn  = (const float*)d_in[5];
    const float* dstw = (const float*)d_in[6];
    const float* dbn  = (const float*)d_in[7];
    const float* pw   = (const float*)d_in[8];
    const float* pb   = (const float*)d_in[9];
    const float* pbn  = (const float*)d_in[10];
    const float* timw = (const float*)d_in[11];
    const float* timb = (const float*)d_in[12];
    float* out   = (float*)d_out;
    float* out_v = out + SZ_X;

    float *pqkv, *pcb, *po, *pp, *pbp, *pbqkv, *pwpf;
    __nv_bfloat16 *pxsb, *pcolb, *pwqkv3, *ptimw3;
    cudaGetSymbolAddress((void**)&pqkv,   g_qkv);
    cudaGetSymbolAddress((void**)&pcb,    g_cb);
    cudaGetSymbolAddress((void**)&po,     g_o);
    cudaGetSymbolAddress((void**)&pp,     g_p);
    cudaGetSymbolAddress((void**)&pbp,    g_bp);
    cudaGetSymbolAddress((void**)&pbqkv,  g_bqkv);
    cudaGetSymbolAddress((void**)&pwpf,   g_wpf);
    cudaGetSymbolAddress((void**)&pxsb,   g_xsb);
    cudaGetSymbolAddress((void**)&pcolb,  g_colb);
    cudaGetSymbolAddress((void**)&pwqkv3, g_wqkv3);
    cudaGetSymbolAddress((void**)&ptimw3, g_timw3);

    const int TB = 256;

    fold_weights<<<(3 * KC * KC + TB - 1) / TB, TB>>>(wq, wk, wv, pw, pb, kbn, vbn, pbn, dstw, dbn);
    split_qkv<<<(3 * KC * KC + TB - 1) / TB, TB>>>();
    split_tim<<<(KC * KC * 5 + TB - 1) / TB, TB>>>(timw);
    lif_in<<<SZ_XT / TB, TB>>>(x);

    // fused q|k|v: M=1152, N=16384, K'=1152, B wraps every 384 (R8 config, occ 1)
    gemm_bf16<128,128,32,64,32,0,384,1,1><<<dim3(128, 9, 1), 256>>>(
        1152, pwqkv3, 1152, 0, pxsb, COLS, 0, pqkv, COLS, 0, pbqkv);

    // fused LIF (+ TIM z seed for t=0, + out_v writes for v)
    lif_qkv_fused<<<3 * SZ_XT / TB, TB>>>(out_v);

    // TIM: sequential over t = 1..3 — GEMM at occupancy 2
    for (int ti = 1; ti < KT; ti++) {
        im2col_k<<<SZ_COL / TB, TB>>>();
        gemm_bf16<64,128,32,32,32,0,1920,0,2><<<dim3(32, 6, 1), 256>>>(
            5760, ptimw3, 5760, 0, pcolb, TCOL, 0, pcb, TCOL, 0, nullptr);
        tim_update<<<SZ_XT / TB, TB>>>(ti, timb);
    }
    tim_final<<<SZ_XT / TB, TB>>>();
    c1_kernel<<<1, 1>>>();

    // dst conv + shared BN (z = h*64 + t*16 + b)
    kt_gemm<<<512, 256>>>();
    vt_gemm<<<512, 256>>>();
    make_qhT<<<SZ_X / TB, TB>>>();

    // fused attn scores + LIF (R8 proven)
    attn_lif_fused<<<dim3(4, 4, 128), 256>>>();

    // fused outT GEMM + identity add -> g_o
    out_fused<<<512, 256>>>(x);

    // proj (exact fp32 FFMA): 384 x 16384 x 384
    gemm_f32<128,128,16,8,8><<<dim3(128, 3, 1), dim3(16, 16)>>>(
        KC, COLS, KC, pwpf, KC, po, COLS, pp, COLS, pbp);

    final_lif<<<SZ_XT / TB, TB>>>(out);
}

// round 15
// speedup vs baseline: 1.6370x; 1.0580x over previous
#include <cuda_runtime.h>
#include <cuda_bf16.h>
#include <cstdint>

// ---------------- problem constants ----------------
constexpr int KT = 4, KB = 16, KC = 384, KN = 256, KH = 8, KD = 48;
constexpr int COLS = KT * KB * KN;     // 16384
constexpr int TCOL = KB * KN;          // 4096
constexpr int SZ_XT = KC * TCOL;       // 1,572,864
constexpr int SZ_X  = KC * COLS;       // 6,291,456
constexpr long long SZ_ATT = (long long)KT * KB * KH * KN * KN;   // 33,554,432
constexpr int SZ_COL = KC * 5 * TCOL;  // 7,864,320

// ---------------- device scratch ----------------
__device__ __align__(16) float g_qkv[3 * SZ_X];     // q|k|v fp32, blocked [c][t*4096+b*256+n]
__device__ __align__(16) float g_cb [SZ_XT];        // tim conv out
__device__ __align__(16) float g_o  [SZ_X];         // out + identity, blocked fp32
__device__ __align__(16) float g_p  [SZ_X];         // proj pre-act [c][16384]

__device__ __align__(16) __nv_bfloat16 g_xsb [SZ_X];          // shortcut spikes bf16 [c][16384]
__device__ __align__(16) __nv_bfloat16 g_zt  [SZ_XT];         // tim z-state bf16 [c][4096]
__device__ __align__(16) __nv_bfloat16 g_colb[SZ_COL];        // im2col bf16
__device__ __align__(16) __nv_bfloat16 g_qhT [SZ_X];          // q heads bf16 [z][d][n]
__device__ __align__(16) __nv_bfloat16 g_amap[SZ_ATT];        // attn map bf16 [z][m][n]
__device__ __align__(16) __nv_bfloat16 g_wqkv3[1152 * 1152];  // qkv weights 3-split along K
__device__ __align__(16) __nv_bfloat16 g_timw3[384 * 5760];
__device__ __align__(16) __nv_bfloat16 g_kt3[512 * 256 * 144];   // [z][m][sp*48+e]
__device__ __align__(16) __nv_bfloat16 g_vt3[512 * 48 * 768];    // [z][d][sp*256+m]

__device__ __align__(16) float g_wqkv[3 * KC * KC];
__device__ float g_bqkv[3 * KC];
__device__ __align__(16) float g_wpf[KC * KC];
__device__ float g_bp[KC];
__device__ float g_dw[KD * KD], g_dwT[KD * KD], g_db[KD];
__device__ float g_cnt[1], g_c1[1];

// ---------------- mma helpers ----------------
__device__ __forceinline__ void ldm_x4(uint32_t& r0, uint32_t& r1, uint32_t& r2, uint32_t& r3, uint32_t addr)
{
    asm volatile("ldmatrix.sync.aligned.m8n8.x4.shared.b16 {%0,%1,%2,%3}, [%4];"
                 : "=r"(r0), "=r"(r1), "=r"(r2), "=r"(r3) : "r"(addr));
}
__device__ __forceinline__ void ldm_x2t(uint32_t& r0, uint32_t& r1, uint32_t addr)
{
    asm volatile("ldmatrix.sync.aligned.m8n8.x2.trans.shared.b16 {%0,%1}, [%2];"
                 : "=r"(r0), "=r"(r1) : "r"(addr));
}
__device__ __forceinline__ void mma_bf16(float* c, const uint32_t* a, const uint32_t* b)
{
    asm volatile("mma.sync.aligned.m16n8k16.row.col.f32.bf16.bf16.f32 "
                 "{%0,%1,%2,%3}, {%4,%5,%6,%7}, {%8,%9}, {%0,%1,%2,%3};"
                 : "+f"(c[0]), "+f"(c[1]), "+f"(c[2]), "+f"(c[3])
                 : "r"(a[0]), "r"(a[1]), "r"(a[2]), "r"(a[3]), "r"(b[0]), "r"(b[1]));
}

// ---------------- bf16 tensor GEMM (register-staged double-buffer core) ----------------
template<int BM, int BN, int BK, int WM, int WN, int CYCA, int CYCB, int HASB, int OCC>
__global__ void __launch_bounds__(256, OCC)
gemm_bf16(int KTOT,
          const __nv_bfloat16* __restrict__ A, int lda, long long sA,
          const __nv_bfloat16* __restrict__ B, int ldb, long long sB,
          float* __restrict__ C, int ldc, long long sC,
          const float* __restrict__ bias)
{
    constexpr int NWM = BM / WM, NWN = BN / WN;
    constexpr int NW = NWM * NWN;
    static_assert(NW == 8, "8 warps");
    constexpr int NT = NW * 32;
    constexpr int MF = WM / 16, NF = WN / 8, KK = BK / 16;
    constexpr int APAD = 8, BPAD = 8;
    __shared__ __align__(16) __nv_bfloat16 As[2][BM][BK + APAD];
    __shared__ __align__(16) __nv_bfloat16 Bs[2][BK][BN + BPAD];

    const int tid = threadIdx.x;
    const int wid = tid >> 5, lane = tid & 31;
    const int wm = (wid / NWN) * WM, wn = (wid % NWN) * WN;
    const int row0 = blockIdx.y * BM, col0 = blockIdx.x * BN;
    const int z = blockIdx.z;
    A += (long long)z * sA;
    B += (long long)z * sB;
    C += (long long)z * sC;

    constexpr int A4 = BM * BK / 8, B4 = BK * BN / 8;
    constexpr int APT = (A4 + NT - 1) / NT, BPT = (B4 + NT - 1) / NT;
    uint4 ar[APT], br[BPT];
    const int ktiles = KTOT / BK;

    auto ldg = [&](int kt) {
        int ka = CYCA ? (kt % (CYCA / BK)) * BK : kt * BK;
        int kb = CYCB ? (kt % (CYCB / BK)) * BK : kt * BK;
#pragma unroll
        for (int u = 0; u < APT; u++) {
            int idx = tid + u * NT;
            if (A4 % NT == 0 || idx < A4) {
                int r = idx / (BK / 8), c8 = idx % (BK / 8);
                ar[u] = *(const uint4*)&A[(long long)(row0 + r) * lda + ka + c8 * 8];
            }
        }
#pragma unroll
        for (int u = 0; u < BPT; u++) {
            int idx = tid + u * NT;
            if (B4 % NT == 0 || idx < B4) {
                int r = idx / (BN / 8), c8 = idx % (BN / 8);
                br[u] = *(const uint4*)&B[(long long)(kb + r) * ldb + col0 + c8 * 8];
            }
        }
    };
    auto sts = [&](int buf) {
#pragma unroll
        for (int u = 0; u < APT; u++) {
            int idx = tid + u * NT;
            if (A4 % NT == 0 || idx < A4) {
                int r = idx / (BK / 8), c8 = idx % (BK / 8);
                *(uint4*)&As[buf][r][c8 * 8] = ar[u];
            }
        }
#pragma unroll
        for (int u = 0; u < BPT; u++) {
            int idx = tid + u * NT;
            if (B4 % NT == 0 || idx < B4) {
                int r = idx / (BN / 8), c8 = idx % (BN / 8);
                *(uint4*)&Bs[buf][r][c8 * 8] = br[u];
            }
        }
    };

    float acc[MF][NF][4];
#pragma unroll
    for (int i = 0; i < MF; i++)
#pragma unroll
        for (int j = 0; j < NF; j++)
#pragma unroll
            for (int q = 0; q < 4; q++) acc[i][j][q] = 0.f;

    auto comp = [&](int buf) {
#pragma unroll
        for (int kk = 0; kk < KK; kk++) {
            uint32_t af[MF][4], bf[NF][2];
#pragma unroll
            for (int mi = 0; mi < MF; mi++) {
                int row = wm + mi * 16 + (lane & 15);
                int col = kk * 16 + (lane >> 4) * 8;
                uint32_t ad = (uint32_t)__cvta_generic_to_shared(&As[buf][row][col]);
                ldm_x4(af[mi][0], af[mi][1], af[mi][2], af[mi][3], ad);
            }
#pragma unroll
            for (int nj = 0; nj < NF; nj++) {
                int r = kk * 16 + (lane & 15);
                int c = wn + nj * 8;
                uint32_t ad = (uint32_t)__cvta_generic_to_shared(&Bs[buf][r][c]);
                ldm_x2t(bf[nj][0], bf[nj][1], ad);
            }
#pragma unroll
            for (int mi = 0; mi < MF; mi++)
#pragma unroll
                for (int nj = 0; nj < NF; nj++)
                    mma_bf16(acc[mi][nj], af[mi], bf[nj]);
        }
    };

    ldg(0); sts(0); __syncthreads();
    int buf = 0;
    for (int kt = 1; kt < ktiles; kt++) {
        ldg(kt);
        comp(buf);
        sts(buf ^ 1);
        __syncthreads();
        buf ^= 1;
    }
    comp(buf);

#pragma unroll
    for (int mi = 0; mi < MF; mi++) {
        int r0 = row0 + wm + mi * 16 + (lane >> 2);
        float b0 = HASB ? bias[r0] : 0.f;
        float b1 = HASB ? bias[r0 + 8] : 0.f;
#pragma unroll
        for (int nj = 0; nj < NF; nj++) {
            int c0 = col0 + wn + nj * 8 + (lane & 3) * 2;
            float2 v0 = {acc[mi][nj][0] + b0, acc[mi][nj][1] + b0};
            float2 v1 = {acc[mi][nj][2] + b1, acc[mi][nj][3] + b1};
            *(float2*)&C[(long long)r0 * ldc + c0] = v0;
            *(float2*)&C[(long long)(r0 + 8) * ldc + c0] = v1;
        }
    }
}

// ---------------- fused attn-score GEMM + LIF (R8 proven) ----------------
__global__ void __launch_bounds__(256, 2)
attn_lif_fused()
{
    constexpr int BM = 64, BN = 64, BK = 16;
    constexpr int NF = 4;
    __shared__ __align__(16) __nv_bfloat16 As[2][BM][BK + 8];
    __shared__ __align__(16) __nv_bfloat16 Bs[2][BK][BN + 8];
    const int tid = threadIdx.x, wid = tid >> 5, lane = tid & 31;
    const int wm = (wid >> 1) * 16, wn = (wid & 1) * 32;
    const int row0 = blockIdx.y * BM, col0 = blockIdx.x * BN;
    const int hb = blockIdx.z, h = hb >> 4, b = hb & 15;

    float acc[4][NF][4];
#pragma unroll
    for (int t = 0; t < 4; t++)
#pragma unroll
        for (int j = 0; j < NF; j++)
#pragma unroll
            for (int q = 0; q < 4; q++) acc[t][j][q] = 0.f;

    for (int t = 0; t < 4; t++) {
        const int z = h * 64 + t * 16 + b;
        const __nv_bfloat16* A = g_kt3 + (long long)z * (256 * 144);
        const __nv_bfloat16* B = g_qhT + (long long)z * (48 * 256);
        uint4 rv;
        auto ldg = [&](int kt) {
            if (tid < 128) {
                int r = tid >> 1, c8 = tid & 1;
                rv = *(const uint4*)&A[(long long)(row0 + r) * 144 + kt * 16 + c8 * 8];
            } else {
                int u = tid & 127;
                int r = u >> 3, c8 = u & 7;
                rv = *(const uint4*)&B[(long long)((kt % 3) * 16 + r) * 256 + col0 + c8 * 8];
            }
        };
        auto sts = [&](int buf) {
            if (tid < 128) { int r = tid >> 1, c8 = tid & 1; *(uint4*)&As[buf][r][c8 * 8] = rv; }
            else { int u = tid & 127; int r = u >> 3, c8 = u & 7; *(uint4*)&Bs[buf][r][c8 * 8] = rv; }
        };
        auto comp = [&](int buf) {
            uint32_t af[4], bf[NF][2];
            {
                int row = wm + (lane & 15);
                int col = (lane >> 4) * 8;
                uint32_t ad = (uint32_t)__cvta_generic_to_shared(&As[buf][row][col]);
                ldm_x4(af[0], af[1], af[2], af[3], ad);
            }
#pragma unroll
            for (int nj = 0; nj < NF; nj++) {
                int r = lane & 15, c = wn + nj * 8;
                uint32_t ad = (uint32_t)__cvta_generic_to_shared(&Bs[buf][r][c]);
                ldm_x2t(bf[nj][0], bf[nj][1], ad);
            }
#pragma unroll
            for (int nj = 0; nj < NF; nj++)
                mma_bf16(acc[t][nj], af, bf[nj]);
        };
        ldg(0); sts(0); __syncthreads();
        int buf = 0;
        for (int kt = 1; kt < 9; kt++) {
            ldg(kt);
            comp(buf);
            sts(buf ^ 1);
            __syncthreads();
            buf ^= 1;
        }
        comp(buf);
        __syncthreads();
    }

    const float c1v = g_c1[0];
    const int m0 = row0 + wm + (lane >> 2);
#pragma unroll
    for (int nj = 0; nj < NF; nj++) {
        int n0 = col0 + wn + nj * 8 + (lane & 3) * 2;
#pragma unroll
        for (int p = 0; p < 2; p++) {
            float v0 = 0.f, v1 = 0.f;
#pragma unroll
            for (int t = 0; t < 4; t++) {
                float x0 = acc[t][nj][p * 2 + 0] * c1v;
                float x1 = acc[t][nj][p * 2 + 1] * c1v;
                v0 += (x0 - v0) * 0.5f;
                v1 += (x1 - v1) * 0.5f;
                float s0 = (v0 >= 0.5f) ? 1.f : 0.f;
                float s1 = (v1 >= 0.5f) ? 1.f : 0.f;
                v0 *= (1.f - s0);
                v1 *= (1.f - s1);
                int z = h * 64 + t * 16 + b;
                __nv_bfloat162 pk = __halves2bfloat162(__float2bfloat16(s0), __float2bfloat16(s1));
                *(__nv_bfloat162*)&g_amap[(long long)z * 65536 + (long long)(m0 + p * 8) * 256 + n0] = pk;
            }
        }
    }
}

// ---------------- fused outT GEMM + identity add (occ 2) ----------------
__global__ void __launch_bounds__(256, 2)
out_fused(const float* __restrict__ x)
{
    constexpr int BM = 48, BN = 256, BK = 32;
    constexpr int MF = 3, NF = 4;
    __shared__ __align__(16) __nv_bfloat16 As[2][BM][BK + 8];
    __shared__ __align__(16) __nv_bfloat16 Bs[2][BK][BN + 8];
    const int tid = threadIdx.x, wid = tid >> 5, lane = tid & 31;
    const int wn = wid * 32;
    const int z = blockIdx.x;
    const int h = z >> 6, t = (z >> 4) & 3, b = z & 15;
    const __nv_bfloat16* A = g_vt3 + (long long)z * (48 * 768);
    const __nv_bfloat16* B = g_amap + (long long)z * 65536;

    uint4 ar, br[4];
    auto ldg = [&](int kt) {
        int ka = kt * BK, kb = (kt % 8) * BK;
        if (tid < 192) { int r = tid >> 2, c8 = tid & 3;
            ar = *(const uint4*)&A[(long long)r * 768 + ka + c8 * 8]; }
#pragma unroll
        for (int u = 0; u < 4; u++) {
            int idx = tid + u * 256;
            int r = idx >> 5, c8 = idx & 31;
            br[u] = *(const uint4*)&B[(long long)(kb + r) * 256 + c8 * 8];
        }
    };
    auto sts = [&](int buf) {
        if (tid < 192) { int r = tid >> 2, c8 = tid & 3; *(uint4*)&As[buf][r][c8 * 8] = ar; }
#pragma unroll
        for (int u = 0; u < 4; u++) {
            int idx = tid + u * 256;
            int r = idx >> 5, c8 = idx & 31;
            *(uint4*)&Bs[buf][r][c8 * 8] = br[u];
        }
    };

    float acc[MF][NF][4];
#pragma unroll
    for (int i = 0; i < MF; i++)
#pragma unroll
        for (int j = 0; j < NF; j++)
#pragma unroll
            for (int q = 0; q < 4; q++) acc[i][j][q] = 0.f;

    auto comp = [&](int buf) {
#pragma unroll
        for (int kk = 0; kk < 2; kk++) {
            uint32_t af[MF][4], bf[NF][2];
#pragma unroll
            for (int mi = 0; mi < MF; mi++) {
                int row = mi * 16 + (lane & 15);
                int col = kk * 16 + (lane >> 4) * 8;
                uint32_t ad = (uint32_t)__cvta_generic_to_shared(&As[buf][row][col]);
                ldm_x4(af[mi][0], af[mi][1], af[mi][2], af[mi][3], ad);
            }
#pragma unroll
            for (int nj = 0; nj < NF; nj++) {
                int r = kk * 16 + (lane & 15), c = wn + nj * 8;
                uint32_t ad = (uint32_t)__cvta_generic_to_shared(&Bs[buf][r][c]);
                ldm_x2t(bf[nj][0], bf[nj][1], ad);
            }
#pragma unroll
            for (int mi = 0; mi < MF; mi++)
#pragma unroll
                for (int nj = 0; nj < NF; nj++)
                    mma_bf16(acc[mi][nj], af[mi], bf[nj]);
        }
    };

    ldg(0); sts(0); __syncthreads();
    int buf = 0;
    for (int kt = 1; kt < 24; kt++) {
        ldg(kt);
        comp(buf);
        sts(buf ^ 1);
        __syncthreads();
        buf ^= 1;
    }
    comp(buf);

#pragma unroll
    for (int mi = 0; mi < MF; mi++) {
        int d0 = mi * 16 + (lane >> 2);
#pragma unroll
        for (int p = 0; p < 2; p++) {
            int d = d0 + p * 8;
            int c = h * 48 + d;
            const float* xr = x + ((long long)(t * 16 + b) * 384 + c) * 256;
            float* orow = g_o + (long long)c * COLS + t * 4096 + b * 256;
#pragma unroll
            for (int nj = 0; nj < NF; nj++) {
                int n = wn + nj * 8 + (lane & 3) * 2;
                float2 xv = *(const float2*)&xr[n];
                float2 v = {acc[mi][nj][p * 2 + 0] + xv.x, acc[mi][nj][p * 2 + 1] + xv.y};
                *(float2*)&orow[n] = v;
            }
        }
    }
}

// ---------------- fp32 GEMM (proj only — exact numerics) ----------------
template<int BM, int BN, int BK, int TM, int TN>
__global__ void __launch_bounds__(256, 2)
gemm_f32(int M, int N, int K,
         const float* __restrict__ A, int lda,
         const float* __restrict__ B, int ldb,
         float* __restrict__ C, int ldc,
         const float* __restrict__ bias)
{
    constexpr int TX = BN / TN, TY = BM / TM, NT = TX * TY;
    constexpr int A4 = BM * BK / 4, B4 = BK * BN / 4;
    constexpr int APT = A4 / NT, BPT = B4 / NT;
    __shared__ __align__(16) float As[2][BK][BM + 4];
    __shared__ __align__(16) float Bs[2][BK][BN];
    const int tx = threadIdx.x, ty = threadIdx.y;
    const int tid = ty * TX + tx;
    const int row0 = blockIdx.y * BM, col0 = blockIdx.x * BN;
    float4 aR[APT], bR[BPT];
    auto ldg = [&](int k0) {
#pragma unroll
        for (int u = 0; u < APT; u++) {
            int idx = tid + u * NT;
            int r = idx / (BK / 4), c4 = idx % (BK / 4);
            aR[u] = *(const float4*)&A[(long long)(row0 + r) * lda + k0 + c4 * 4];
        }
#pragma unroll
        for (int u = 0; u < BPT; u++) {
            int idx = tid + u * NT;
            int kk = idx / (BN / 4), n4 = idx % (BN / 4);
            bR[u] = *(const float4*)&B[(long long)(k0 + kk) * ldb + col0 + n4 * 4];
        }
    };
    auto sts = [&](int buf) {
#pragma unroll
        for (int u = 0; u < APT; u++) {
            int idx = tid + u * NT;
            int r = idx / (BK / 4), c4 = idx % (BK / 4);
            As[buf][c4 * 4 + 0][r] = aR[u].x;
            As[buf][c4 * 4 + 1][r] = aR[u].y;
            As[buf][c4 * 4 + 2][r] = aR[u].z;
            As[buf][c4 * 4 + 3][r] = aR[u].w;
        }
#pragma unroll
        for (int u = 0; u < BPT; u++) {
            int idx = tid + u * NT;
            int kk = idx / (BN / 4), n4 = idx % (BN / 4);
            *(float4*)&Bs[buf][kk][n4 * 4] = bR[u];
        }
    };
    float acc[TM][TN];
#pragma unroll
    for (int i = 0; i < TM; i++)
#pragma unroll
        for (int j = 0; j < TN; j++) acc[i][j] = 0.f;
    auto comp = [&](int buf) {
#pragma unroll
        for (int kk = 0; kk < BK; kk++) {
            float a[TM], b[TN];
#pragma unroll
            for (int i4 = 0; i4 < TM / 4; i4++) {
                float4 v = *(const float4*)&As[buf][kk][ty * TM + i4 * 4];
                a[i4*4+0]=v.x; a[i4*4+1]=v.y; a[i4*4+2]=v.z; a[i4*4+3]=v.w;
            }
#pragma unroll
            for (int j4 = 0; j4 < TN / 4; j4++) {
                float4 v = *(const float4*)&Bs[buf][kk][tx * TN + j4 * 4];
                b[j4*4+0]=v.x; b[j4*4+1]=v.y; b[j4*4+2]=v.z; b[j4*4+3]=v.w;
            }
#pragma unroll
            for (int i = 0; i < TM; i++)
#pragma unroll
                for (int j = 0; j < TN; j++)
                    acc[i][j] = fmaf(a[i], b[j], acc[i][j]);
        }
    };
    ldg(0); sts(0); __syncthreads();
    const int nit = K / BK;
    int buf = 0;
    for (int it = 1; it < nit; it++) {
        ldg(it * BK); comp(buf); sts(buf ^ 1); __syncthreads(); buf ^= 1;
    }
    comp(buf);
#pragma unroll
    for (int i = 0; i < TM; i++) {
        int r = row0 + ty * TM + i;
        float bv = bias ? bias[r] : 0.f;
#pragma unroll
        for (int j4 = 0; j4 < TN / 4; j4++) {
            float4 v;
            v.x = acc[i][j4*4+0] + bv; v.y = acc[i][j4*4+1] + bv;
            v.z = acc[i][j4*4+2] + bv; v.w = acc[i][j4*4+3] + bv;
            *(float4*)&C[(long long)r * ldc + col0 + tx * TN + j4 * 4] = v;
        }
    }
}

// ---------------- split helper ----------------
__device__ __forceinline__ void split3f(float x, __nv_bfloat16& h, __nv_bfloat16& m, __nv_bfloat16& l)
{
    __nv_bfloat16 bh = __float2bfloat16(x);
    float r1 = x - __bfloat162float(bh);
    __nv_bfloat16 bm = __float2bfloat16(r1);
    float r2 = r1 - __bfloat162float(bm);
    h = bh; m = bm; l = __float2bfloat16(r2);
}

// ---------------- BN folding ----------------
__global__ void fold_weights(const float* __restrict__ wq, const float* __restrict__ wk,
                             const float* __restrict__ wv, const float* __restrict__ pw,
                             const float* __restrict__ pb, const float* __restrict__ kbn,
                             const float* __restrict__ vbn, const float* __restrict__ pbn,
                             const float* __restrict__ dstw, const float* __restrict__ dbn)
{
    int i = blockIdx.x * blockDim.x + threadIdx.x;
    if (i == 0) g_cnt[0] = 0.f;
    if (i < 3 * KC * KC) {
        int rr = i / KC, c = i % KC;
        float w;
        if (rr < KC) w = wq[rr * KC + c];
        else if (rr < 2 * KC) { int d = rr - KC;     w = kbn[d] * rsqrtf(kbn[3*KC + d] + 1e-5f) * wk[d * KC + c]; }
        else                  { int d = rr - 2 * KC; w = vbn[d] * rsqrtf(vbn[3*KC + d] + 1e-5f) * wv[d * KC + c]; }
        g_wqkv[i] = w;
    }
    if (i < KC * KC) {
        int d = i / KC;
        g_wpf[i] = pbn[d] * rsqrtf(pbn[3*KC + d] + 1e-5f) * pw[i];
    }
    if (i < 3 * KC) {
        float bvv;
        if (i < KC) bvv = 0.f;
        else if (i < 2 * KC) { int d = i - KC;     float inv = kbn[d] * rsqrtf(kbn[3*KC+d] + 1e-5f); bvv = kbn[KC + d] - inv * kbn[2*KC + d]; }
        else                 { int d = i - 2 * KC; float inv = vbn[d] * rsqrtf(vbn[3*KC+d] + 1e-5f); bvv = vbn[KC + d] - inv * vbn[2*KC + d]; }
        g_bqkv[i] = bvv;
    }
    if (i < KC) {
        float inv = pbn[i] * rsqrtf(pbn[3*KC + i] + 1e-5f);
        g_bp[i] = pbn[KC + i] + inv * (pb[i] - pbn[2*KC + i]);
    }
    if (i < KD * KD) {
        int e = i / KD, d = i % KD;
        float inv = dbn[e] * rsqrtf(dbn[3*KD + e] + 1e-5f);
        float wf = inv * dstw[i];
        g_dw[i] = wf;
        g_dwT[d * KD + e] = wf;
    }
    if (i < KD) {
        float inv = dbn[i] * rsqrtf(dbn[3*KD + i] + 1e-5f);
        g_db[i] = dbn[KD + i] - inv * dbn[2*KD + i];
    }
}

__global__ void split_qkv()
{
    int i = blockIdx.x * blockDim.x + threadIdx.x;
    if (i >= 3 * KC * KC) return;
    int r = i / KC, c = i % KC;
    __nv_bfloat16 h, m, l;
    split3f(g_wqkv[i], h, m, l);
    __nv_bfloat16* row = g_wqkv3 + (long long)r * 1152;
    row[c] = h; row[KC + c] = m; row[2 * KC + c] = l;
}

__global__ void split_tim(const float* __restrict__ timw)
{
    int i = blockIdx.x * blockDim.x + threadIdx.x;
    if (i >= KC * KC * 5) return;
    int r = i / (KC * 5), c = i % (KC * 5);
    __nv_bfloat16 h, m, l;
    split3f(timw[i], h, m, l);
    __nv_bfloat16* row = g_timw3 + (long long)r * 5760;
    row[c] = h; row[1920 + c] = m; row[3840 + c] = l;
}

// ---------------- LIF kernels ----------------
__global__ void lif_in(const float* __restrict__ x)
{
    int i = blockIdx.x * blockDim.x + threadIdx.x;
    if (i >= SZ_XT) return;
    int c = i >> 12, j = i & 4095, b = j >> 8, n = j & 255;
    const float* xp = x + ((long long)b * KC + c) * KN + n;
    __nv_bfloat16* o = g_xsb + (long long)c * COLS + j;
    float v = 0.f;
#pragma unroll
    for (int t = 0; t < KT; t++) {
        float xv = xp[(long long)t * KB * KC * KN];
        v += (xv - v) * 0.5f;
        float s = (v >= 1.f) ? 1.f : 0.f;
        o[t * TCOL] = __float2bfloat16(s);
        v *= (1.f - s);
    }
}

// fused LIF over q|k|v; region 0 seeds TIM z-state (t=0), region 2 writes out_v
__global__ void lif_qkv_fused(float* __restrict__ outv)
{
    int i = blockIdx.x * blockDim.x + threadIdx.x;
    if (i >= 3 * SZ_XT) return;
    int region = i / SZ_XT;
    int il = i - region * SZ_XT;
    int c = il >> 12, j = il & 4095;
    float vth = (region == 0) ? 0.05f : 1.0f;
    float* buf = g_qkv + (long long)region * SZ_X;
    long long o = ((long long)c) * COLS + j;
    int b = j >> 8, n = j & 255;
    int h = c / KD, d = c - h * KD;
    float v = 0.f;
#pragma unroll
    for (int t = 0; t < KT; t++) {
        long long a = o + t * TCOL;
        float xv = buf[a];
        v += (xv - v) * 0.5f;
        float s = (v >= vth) ? 1.f : 0.f;
        buf[a] = s;
        v *= (1.f - s);
        if (region == 0 && t == 0)
            g_zt[c * TCOL + j] = __float2bfloat16(5.0f * s);
        if (region == 2)
            outv[(((long long)(t * KB + b) * KH + h) * KN + n) * KD + d] = s;
    }
}

// ---------------- TIM ----------------
__global__ void im2col_k()
{
    int i = blockIdx.x * blockDim.x + threadIdx.x;
    if (i >= SZ_COL) return;
    int j = i & 4095, r = i >> 12;
    int kk = r % 5, ci = r / 5;
    int n = j & 255;
    int n2 = n + kk - 2;
    __nv_bfloat16 v = __float2bfloat16(0.f);
    if (n2 >= 0 && n2 < KN) v = g_zt[ci * TCOL + (j - n) + n2];
    g_colb[i] = v;
}

__global__ void tim_update(int ti, const float* __restrict__ timb)
{
    int i = blockIdx.x * blockDim.x + threadIdx.x;
    if (i >= SZ_XT) return;
    int c = i >> 12, j = i & 4095;
    float cv = 0.2f * g_cb[i] + timb[c];
    float s = (cv * 0.5f >= 0.3f) ? 1.f : 0.f;
    long long qa = (long long)c * COLS + ti * TCOL + j;
    float q = g_qkv[qa];
    float xt = s * 0.6f + q * 0.4f;
    g_qkv[qa] = xt;
    g_zt[i] = __float2bfloat16(3.0f * s + 2.0f * q);
}

// final TIM LIF: writes q spikes DIRECTLY into qhT head layout (bf16) + spike count
__global__ void tim_final_qh()
{
    int i = blockIdx.x * blockDim.x + threadIdx.x;
    int cnt = 0;
    if (i < SZ_XT) {
        int c = i >> 12, j = i & 4095;
        int b = j >> 8, n = j & 255;
        int h = c / KD, d = c - h * KD;
        const float* q = g_qkv + (long long)c * COLS + j;
        float v = 0.f;
#pragma unroll
        for (int t = 0; t < KT; t++) {
            float xv = q[t * TCOL];
            v += (xv - v) * 0.5f;
            float s = (v >= 0.5f) ? 1.f : 0.f;
            int z = h * 64 + t * 16 + b;
            g_qhT[((long long)z * KD + d) * KN + n] = __float2bfloat16(s);
            cnt += (int)s;
            v *= (1.f - s);
        }
    }
#pragma unroll
    for (int o = 16; o > 0; o >>= 1) cnt += __shfl_down_sync(0xffffffffu, cnt, o);
    if ((threadIdx.x & 31) == 0 && cnt) atomicAdd(&g_cnt[0], (float)cnt);
}

__global__ void c1_kernel()
{
    float mean = g_cnt[0] / 6291456.0f;
    g_c1[0] = fminf(1.0f / sqrtf(mean * 48.0f + 1e-6f), 10.0f);
}

// ---------------- dst conv (48x48): ktT3 [z][m][sp*48+e], vtT3 [z][d][sp*256+m] ----------------
__global__ void kt_gemm()
{
    int z = blockIdx.x;                 // z = h*64 + t*16 + b
    int h = z >> 6, t = (z >> 4) & 3, b = z & 15;
    int m = threadIdx.x;
    __shared__ float A[KD * KD];
    __shared__ float bs[KD];
    for (int idx = m; idx < KD * KD; idx += 256) A[idx] = g_dw[idx];
    if (m < KD) bs[m] = g_db[m];
    __syncthreads();
    const float* kp = g_qkv + SZ_X + (long long)(h * KD) * COLS + t * TCOL + b * KN + m;
    float kd[KD];
#pragma unroll
    for (int d = 0; d < KD; d++) kd[d] = kp[(long long)d * COLS];
    float s[KD];
#pragma unroll
    for (int e = 0; e < KD; e++) {
        float acc = bs[e];
#pragma unroll
        for (int d = 0; d < KD; d++) acc = fmaf(A[e * KD + d], kd[d], acc);
        s[e] = acc;
    }
    uint2* dst = (uint2*)(g_kt3 + (long long)z * (256 * 144) + m * 144);
#pragma unroll
    for (int sp = 0; sp < 3; sp++) {
#pragma unroll
        for (int w = 0; w < 12; w++) {
            __nv_bfloat16 t0 = __float2bfloat16(s[w*4+0]); s[w*4+0] -= __bfloat162float(t0);
            __nv_bfloat16 t1 = __float2bfloat16(s[w*4+1]); s[w*4+1] -= __bfloat162float(t1);
            __nv_bfloat16 t2 = __float2bfloat16(s[w*4+2]); s[w*4+2] -= __bfloat162float(t2);
            __nv_bfloat16 t3 = __float2bfloat16(s[w*4+3]); s[w*4+3] -= __bfloat162float(t3);
            __nv_bfloat162 p01 = __halves2bfloat162(t0, t1);
            __nv_bfloat162 p23 = __halves2bfloat162(t2, t3);
            uint2 u;
            u.x = *reinterpret_cast<uint32_t*>(&p01);
            u.y = *reinterpret_cast<uint32_t*>(&p23);
            dst[sp * 12 + w] = u;
        }
    }
}

__global__ void vt_gemm()
{
    int z = blockIdx.x;
    int h = z >> 6, t = (z >> 4) & 3, b = z & 15;
    int m = threadIdx.x;
    __shared__ float BT[KD * KD];
    __shared__ float bs[KD];
    for (int idx = m; idx < KD * KD; idx += 256) BT[idx] = g_dwT[idx];
    if (m < KD) bs[m] = g_db[m];
    __syncthreads();
    const float* vp = g_qkv + 2 * SZ_X + (long long)(h * KD) * COLS + t * TCOL + b * KN + m;
    float r[KD];
#pragma unroll
    for (int d = 0; d < KD; d++) r[d] = vp[(long long)d * COLS];
    __nv_bfloat16* Cp = g_vt3 + (long long)z * (48 * 768) + m;
#pragma unroll
    for (int e = 0; e < KD; e++) {
        float s = bs[e];
#pragma unroll
        for (int d = 0; d < KD; d++) s = fmaf(r[d], BT[d * KD + e], s);
        __nv_bfloat16 hh = __float2bfloat16(s); s -= __bfloat162float(hh);
        __nv_bfloat16 mm = __float2bfloat16(s); s -= __bfloat162float(mm);
        __nv_bfloat16 ll = __float2bfloat16(s);
        Cp[e * 768]       = hh;
        Cp[e * 768 + 256] = mm;
        Cp[e * 768 + 512] = ll;
    }
}

// ---------------- final LIF ----------------
__global__ void final_lif(float* __restrict__ out)
{
    int i = blockIdx.x * blockDim.x + threadIdx.x;
    if (i >= SZ_XT) return;
    int c = i >> 12, j = i & 4095, b = j >> 8, n = j & 255;
    const float* p = g_p + (long long)c * COLS + j;
    float* o = out + ((long long)b * KC + c) * KN + n;
    float v = 0.f;
#pragma unroll
    for (int t = 0; t < KT; t++) {
        float xv = p[t * TCOL];
        v += (xv - v) * 0.5f;
        float s = (v >= 1.f) ? 1.f : 0.f;
        o[(long long)t * KB * KC * KN] = s;
        v *= (1.f - s);
    }
}

// ---------------- host launcher ----------------
extern "C" void kernel_launch(void* const* d_in, const int* in_sizes, int n_in,
                              void* d_out, int out_size)
{
    (void)in_sizes; (void)n_in; (void)out_size;
    const float* x    = (const float*)d_in[0];
    const float* wq   = (const float*)d_in[1];
    const float* wk   = (const float*)d_in[2];
    const float* wv   = (const float*)d_in[3];
    const float* kbn  = (const float*)d_in[4];
    const float* vbn  = (const float*)d_in[5];
    const float* dstw = (const float*)d_in[6];
    const float* dbn  = (const float*)d_in[7];
    const float* pw   = (const float*)d_in[8];
    const float* pb   = (const float*)d_in[9];
    const float* pbn  = (const float*)d_in[10];
    const float* timw = (const float*)d_in[11];
    const float* timb = (const float*)d_in[12];
    float* out   = (float*)d_out;
    float* out_v = out + SZ_X;

    float *pqkv, *pcb, *po, *pp, *pbp, *pbqkv, *pwpf;
    __nv_bfloat16 *pxsb, *pcolb, *pwqkv3, *ptimw3;
    cudaGetSymbolAddress((void**)&pqkv,   g_qkv);
    cudaGetSymbolAddress((void**)&pcb,    g_cb);
    cudaGetSymbolAddress((void**)&po,     g_o);
    cudaGetSymbolAddress((void**)&pp,     g_p);
    cudaGetSymbolAddress((void**)&pbp,    g_bp);
    cudaGetSymbolAddress((void**)&pbqkv,  g_bqkv);
    cudaGetSymbolAddress((void**)&pwpf,   g_wpf);
    cudaGetSymbolAddress((void**)&pxsb,   g_xsb);
    cudaGetSymbolAddress((void**)&pcolb,  g_colb);
    cudaGetSymbolAddress((void**)&pwqkv3, g_wqkv3);
    cudaGetSymbolAddress((void**)&ptimw3, g_timw3);

    const int TB = 256;

    fold_weights<<<(3 * KC * KC + TB - 1) / TB, TB>>>(wq, wk, wv, pw, pb, kbn, vbn, pbn, dstw, dbn);
    split_qkv<<<(3 * KC * KC + TB - 1) / TB, TB>>>();
    split_tim<<<(KC * KC * 5 + TB - 1) / TB, TB>>>(timw);
    lif_in<<<SZ_XT / TB, TB>>>(x);

    // fused q|k|v: M=1152, N=16384, K'=1152, B wraps every 384 — occupancy 2
    gemm_bf16<128,128,32,64,32,0,384,1,2><<<dim3(128, 9, 1), 256>>>(
        1152, pwqkv3, 1152, 0, pxsb, COLS, 0, pqkv, COLS, 0, pbqkv);

    // fused LIF (+ TIM z seed for t=0, + out_v writes for v)
    lif_qkv_fused<<<3 * SZ_XT / TB, TB>>>(out_v);

    // TIM: sequential over t = 1..3 — GEMM at occupancy 2
    for (int ti = 1; ti < KT; ti++) {
        im2col_k<<<SZ_COL / TB, TB>>>();
        gemm_bf16<64,128,32,32,32,0,1920,0,2><<<dim3(32, 6, 1), 256>>>(
            5760, ptimw3, 5760, 0, pcolb, TCOL, 0, pcb, TCOL, 0, nullptr);
        tim_update<<<SZ_XT / TB, TB>>>(ti, timb);
    }
    // final TIM LIF writes qhT directly (make_qhT pass eliminated)
    tim_final_qh<<<SZ_XT / TB, TB>>>();
    c1_kernel<<<1, 1>>>();

    // dst conv + shared BN (z = h*64 + t*16 + b)
    kt_gemm<<<512, 256>>>();
    vt_gemm<<<512, 256>>>();

    // fused attn scores + LIF
    attn_lif_fused<<<dim3(4, 4, 128), 256>>>();

    // fused outT GEMM + identity add -> g_o (occ 2)
    out_fused<<<512, 256>>>(x);

    // proj (exact fp32 FFMA): 384 x 16384 x 384
    gemm_f32<128,128,16,8,8><<<dim3(128, 3, 1), dim3(16, 16)>>>(
        KC, COLS, KC, pwpf, KC, po, COLS, pp, COLS, pbp);

    final_lif<<<SZ_XT / TB, TB>>>(out);
}

// round 16
// speedup vs baseline: 1.6690x; 1.0196x over previous
#include <cuda_runtime.h>
#include <cuda_bf16.h>
#include <cstdint>

// ---------------- problem constants ----------------
constexpr int KT = 4, KB = 16, KC = 384, KN = 256, KH = 8, KD = 48;
constexpr int COLS = KT * KB * KN;     // 16384
constexpr int TCOL = KB * KN;          // 4096
constexpr int SZ_XT = KC * TCOL;       // 1,572,864
constexpr int SZ_X  = KC * COLS;       // 6,291,456
constexpr long long SZ_ATT = (long long)KT * KB * KH * KN * KN;   // 33,554,432
constexpr int SZ_COL = KC * 5 * TCOL;  // 7,864,320

// ---------------- device scratch ----------------
__device__ __align__(16) float g_qkv[3 * SZ_X];     // q|k|v fp32, blocked [c][t*4096+b*256+n]
__device__ __align__(16) float g_cb [SZ_XT];        // tim conv out
__device__ __align__(16) float g_o  [SZ_X];         // out + identity, blocked fp32
__device__ __align__(16) float g_p  [SZ_X];         // proj pre-act [c][16384]

__device__ __align__(16) __nv_bfloat16 g_xsb [SZ_X];          // shortcut spikes bf16 [c][16384]
__device__ __align__(16) __nv_bfloat16 g_zt  [SZ_XT];         // tim z-state bf16 [c][4096] (seed only)
__device__ __align__(16) __nv_bfloat16 g_colb[SZ_COL];        // im2col bf16
__device__ __align__(16) __nv_bfloat16 g_qhT [SZ_X];          // q heads bf16 [z][d][n]
__device__ __align__(16) __nv_bfloat16 g_amap[SZ_ATT];        // attn map bf16 [z][m][n]
__device__ __align__(16) __nv_bfloat16 g_wqkv3[1152 * 1152];  // qkv weights 3-split along K
__device__ __align__(16) __nv_bfloat16 g_timw3[384 * 5760];
__device__ __align__(16) __nv_bfloat16 g_kt3[512 * 256 * 144];   // [z][m][sp*48+e]
__device__ __align__(16) __nv_bfloat16 g_vt3[512 * 48 * 768];    // [z][d][sp*256+m]

__device__ __align__(16) float g_wqkv[3 * KC * KC];
__device__ float g_bqkv[3 * KC];
__device__ __align__(16) float g_wpf[KC * KC];
__device__ float g_bp[KC];
__device__ float g_dw[KD * KD], g_dwT[KD * KD], g_db[KD];
__device__ float g_cnt[1], g_c1[1];

// ---------------- mma helpers ----------------
__device__ __forceinline__ void ldm_x4(uint32_t& r0, uint32_t& r1, uint32_t& r2, uint32_t& r3, uint32_t addr)
{
    asm volatile("ldmatrix.sync.aligned.m8n8.x4.shared.b16 {%0,%1,%2,%3}, [%4];"
                 : "=r"(r0), "=r"(r1), "=r"(r2), "=r"(r3) : "r"(addr));
}
__device__ __forceinline__ void ldm_x2t(uint32_t& r0, uint32_t& r1, uint32_t addr)
{
    asm volatile("ldmatrix.sync.aligned.m8n8.x2.trans.shared.b16 {%0,%1}, [%2];"
                 : "=r"(r0), "=r"(r1) : "r"(addr));
}
__device__ __forceinline__ void mma_bf16(float* c, const uint32_t* a, const uint32_t* b)
{
    asm volatile("mma.sync.aligned.m16n8k16.row.col.f32.bf16.bf16.f32 "
                 "{%0,%1,%2,%3}, {%4,%5,%6,%7}, {%8,%9}, {%0,%1,%2,%3};"
                 : "+f"(c[0]), "+f"(c[1]), "+f"(c[2]), "+f"(c[3])
                 : "r"(a[0]), "r"(a[1]), "r"(a[2]), "r"(a[3]), "r"(b[0]), "r"(b[1]));
}

// ---------------- bf16 tensor GEMM (register-staged double-buffer core) ----------------
template<int BM, int BN, int BK, int WM, int WN, int CYCA, int CYCB, int HASB, int OCC>
__global__ void __launch_bounds__(256, OCC)
gemm_bf16(int KTOT,
          const __nv_bfloat16* __restrict__ A, int lda, long long sA,
          const __nv_bfloat16* __restrict__ B, int ldb, long long sB,
          float* __restrict__ C, int ldc, long long sC,
          const float* __restrict__ bias)
{
    constexpr int NWM = BM / WM, NWN = BN / WN;
    constexpr int NW = NWM * NWN;
    static_assert(NW == 8, "8 warps");
    constexpr int NT = NW * 32;
    constexpr int MF = WM / 16, NF = WN / 8, KK = BK / 16;
    constexpr int APAD = 8, BPAD = 8;
    __shared__ __align__(16) __nv_bfloat16 As[2][BM][BK + APAD];
    __shared__ __align__(16) __nv_bfloat16 Bs[2][BK][BN + BPAD];

    const int tid = threadIdx.x;
    const int wid = tid >> 5, lane = tid & 31;
    const int wm = (wid / NWN) * WM, wn = (wid % NWN) * WN;
    const int row0 = blockIdx.y * BM, col0 = blockIdx.x * BN;
    const int z = blockIdx.z;
    A += (long long)z * sA;
    B += (long long)z * sB;
    C += (long long)z * sC;

    constexpr int A4 = BM * BK / 8, B4 = BK * BN / 8;
    constexpr int APT = (A4 + NT - 1) / NT, BPT = (B4 + NT - 1) / NT;
    uint4 ar[APT], br[BPT];
    const int ktiles = KTOT / BK;

    auto ldg = [&](int kt) {
        int ka = CYCA ? (kt % (CYCA / BK)) * BK : kt * BK;
        int kb = CYCB ? (kt % (CYCB / BK)) * BK : kt * BK;
#pragma unroll
        for (int u = 0; u < APT; u++) {
            int idx = tid + u * NT;
            if (A4 % NT == 0 || idx < A4) {
                int r = idx / (BK / 8), c8 = idx % (BK / 8);
                ar[u] = *(const uint4*)&A[(long long)(row0 + r) * lda + ka + c8 * 8];
            }
        }
#pragma unroll
        for (int u = 0; u < BPT; u++) {
            int idx = tid + u * NT;
            if (B4 % NT == 0 || idx < B4) {
                int r = idx / (BN / 8), c8 = idx % (BN / 8);
                br[u] = *(const uint4*)&B[(long long)(kb + r) * ldb + col0 + c8 * 8];
            }
        }
    };
    auto sts = [&](int buf) {
#pragma unroll
        for (int u = 0; u < APT; u++) {
            int idx = tid + u * NT;
            if (A4 % NT == 0 || idx < A4) {
                int r = idx / (BK / 8), c8 = idx % (BK / 8);
                *(uint4*)&As[buf][r][c8 * 8] = ar[u];
            }
        }
#pragma unroll
        for (int u = 0; u < BPT; u++) {
            int idx = tid + u * NT;
            if (B4 % NT == 0 || idx < B4) {
                int r = idx / (BN / 8), c8 = idx % (BN / 8);
                *(uint4*)&Bs[buf][r][c8 * 8] = br[u];
            }
        }
    };

    float acc[MF][NF][4];
#pragma unroll
    for (int i = 0; i < MF; i++)
#pragma unroll
        for (int j = 0; j < NF; j++)
#pragma unroll
            for (int q = 0; q < 4; q++) acc[i][j][q] = 0.f;

    auto comp = [&](int buf) {
#pragma unroll
        for (int kk = 0; kk < KK; kk++) {
            uint32_t af[MF][4], bf[NF][2];
#pragma unroll
            for (int mi = 0; mi < MF; mi++) {
                int row = wm + mi * 16 + (lane & 15);
                int col = kk * 16 + (lane >> 4) * 8;
                uint32_t ad = (uint32_t)__cvta_generic_to_shared(&As[buf][row][col]);
                ldm_x4(af[mi][0], af[mi][1], af[mi][2], af[mi][3], ad);
            }
#pragma unroll
            for (int nj = 0; nj < NF; nj++) {
                int r = kk * 16 + (lane & 15);
                int c = wn + nj * 8;
                uint32_t ad = (uint32_t)__cvta_generic_to_shared(&Bs[buf][r][c]);
                ldm_x2t(bf[nj][0], bf[nj][1], ad);
            }
#pragma unroll
            for (int mi = 0; mi < MF; mi++)
#pragma unroll
                for (int nj = 0; nj < NF; nj++)
                    mma_bf16(acc[mi][nj], af[mi], bf[nj]);
        }
    };

    ldg(0); sts(0); __syncthreads();
    int buf = 0;
    for (int kt = 1; kt < ktiles; kt++) {
        ldg(kt);
        comp(buf);
        sts(buf ^ 1);
        __syncthreads();
        buf ^= 1;
    }
    comp(buf);

#pragma unroll
    for (int mi = 0; mi < MF; mi++) {
        int r0 = row0 + wm + mi * 16 + (lane >> 2);
        float b0 = HASB ? bias[r0] : 0.f;
        float b1 = HASB ? bias[r0 + 8] : 0.f;
#pragma unroll
        for (int nj = 0; nj < NF; nj++) {
            int c0 = col0 + wn + nj * 8 + (lane & 3) * 2;
            float2 v0 = {acc[mi][nj][0] + b0, acc[mi][nj][1] + b0};
            float2 v1 = {acc[mi][nj][2] + b1, acc[mi][nj][3] + b1};
            *(float2*)&C[(long long)r0 * ldc + c0] = v0;
            *(float2*)&C[(long long)(r0 + 8) * ldc + c0] = v1;
        }
    }
}

// ---------------- fused attn-score GEMM + LIF ----------------
__global__ void __launch_bounds__(256, 2)
attn_lif_fused()
{
    constexpr int BM = 64, BN = 64, BK = 16;
    constexpr int NF = 4;
    __shared__ __align__(16) __nv_bfloat16 As[2][BM][BK + 8];
    __shared__ __align__(16) __nv_bfloat16 Bs[2][BK][BN + 8];
    const int tid = threadIdx.x, wid = tid >> 5, lane = tid & 31;
    const int wm = (wid >> 1) * 16, wn = (wid & 1) * 32;
    const int row0 = blockIdx.y * BM, col0 = blockIdx.x * BN;
    const int hb = blockIdx.z, h = hb >> 4, b = hb & 15;

    float acc[4][NF][4];
#pragma unroll
    for (int t = 0; t < 4; t++)
#pragma unroll
        for (int j = 0; j < NF; j++)
#pragma unroll
            for (int q = 0; q < 4; q++) acc[t][j][q] = 0.f;

    for (int t = 0; t < 4; t++) {
        const int z = h * 64 + t * 16 + b;
        const __nv_bfloat16* A = g_kt3 + (long long)z * (256 * 144);
        const __nv_bfloat16* B = g_qhT + (long long)z * (48 * 256);
        uint4 rv;
        auto ldg = [&](int kt) {
            if (tid < 128) {
                int r = tid >> 1, c8 = tid & 1;
                rv = *(const uint4*)&A[(long long)(row0 + r) * 144 + kt * 16 + c8 * 8];
            } else {
                int u = tid & 127;
                int r = u >> 3, c8 = u & 7;
                rv = *(const uint4*)&B[(long long)((kt % 3) * 16 + r) * 256 + col0 + c8 * 8];
            }
        };
        auto sts = [&](int buf) {
            if (tid < 128) { int r = tid >> 1, c8 = tid & 1; *(uint4*)&As[buf][r][c8 * 8] = rv; }
            else { int u = tid & 127; int r = u >> 3, c8 = u & 7; *(uint4*)&Bs[buf][r][c8 * 8] = rv; }
        };
        auto comp = [&](int buf) {
            uint32_t af[4], bf[NF][2];
            {
                int row = wm + (lane & 15);
                int col = (lane >> 4) * 8;
                uint32_t ad = (uint32_t)__cvta_generic_to_shared(&As[buf][row][col]);
                ldm_x4(af[0], af[1], af[2], af[3], ad);
            }
#pragma unroll
            for (int nj = 0; nj < NF; nj++) {
                int r = lane & 15, c = wn + nj * 8;
                uint32_t ad = (uint32_t)__cvta_generic_to_shared(&Bs[buf][r][c]);
                ldm_x2t(bf[nj][0], bf[nj][1], ad);
            }
#pragma unroll
            for (int nj = 0; nj < NF; nj++)
                mma_bf16(acc[t][nj], af, bf[nj]);
        };
        ldg(0); sts(0); __syncthreads();
        int buf = 0;
        for (int kt = 1; kt < 9; kt++) {
            ldg(kt);
            comp(buf);
            sts(buf ^ 1);
            __syncthreads();
            buf ^= 1;
        }
        comp(buf);
        __syncthreads();
    }

    const float c1v = g_c1[0];
    const int m0 = row0 + wm + (lane >> 2);
#pragma unroll
    for (int nj = 0; nj < NF; nj++) {
        int n0 = col0 + wn + nj * 8 + (lane & 3) * 2;
#pragma unroll
        for (int p = 0; p < 2; p++) {
            float v0 = 0.f, v1 = 0.f;
#pragma unroll
            for (int t = 0; t < 4; t++) {
                float x0 = acc[t][nj][p * 2 + 0] * c1v;
                float x1 = acc[t][nj][p * 2 + 1] * c1v;
                v0 += (x0 - v0) * 0.5f;
                v1 += (x1 - v1) * 0.5f;
                float s0 = (v0 >= 0.5f) ? 1.f : 0.f;
                float s1 = (v1 >= 0.5f) ? 1.f : 0.f;
                v0 *= (1.f - s0);
                v1 *= (1.f - s1);
                int z = h * 64 + t * 16 + b;
                __nv_bfloat162 pk = __halves2bfloat162(__float2bfloat16(s0), __float2bfloat16(s1));
                *(__nv_bfloat162*)&g_amap[(long long)z * 65536 + (long long)(m0 + p * 8) * 256 + n0] = pk;
            }
        }
    }
}

// ---------------- fused outT GEMM + identity add (occ 2) ----------------
__global__ void __launch_bounds__(256, 2)
out_fused(const float* __restrict__ x)
{
    constexpr int BM = 48, BN = 256, BK = 32;
    constexpr int MF = 3, NF = 4;
    __shared__ __align__(16) __nv_bfloat16 As[2][BM][BK + 8];
    __shared__ __align__(16) __nv_bfloat16 Bs[2][BK][BN + 8];
    const int tid = threadIdx.x, wid = tid >> 5, lane = tid & 31;
    const int wn = wid * 32;
    const int z = blockIdx.x;
    const int h = z >> 6, t = (z >> 4) & 3, b = z & 15;
    const __nv_bfloat16* A = g_vt3 + (long long)z * (48 * 768);
    const __nv_bfloat16* B = g_amap + (long long)z * 65536;

    uint4 ar, br[4];
    auto ldg = [&](int kt) {
        int ka = kt * BK, kb = (kt % 8) * BK;
        if (tid < 192) { int r = tid >> 2, c8 = tid & 3;
            ar = *(const uint4*)&A[(long long)r * 768 + ka + c8 * 8]; }
#pragma unroll
        for (int u = 0; u < 4; u++) {
            int idx = tid + u * 256;
            int r = idx >> 5, c8 = idx & 31;
            br[u] = *(const uint4*)&B[(long long)(kb + r) * 256 + c8 * 8];
        }
    };
    auto sts = [&](int buf) {
        if (tid < 192) { int r = tid >> 2, c8 = tid & 3; *(uint4*)&As[buf][r][c8 * 8] = ar; }
#pragma unroll
        for (int u = 0; u < 4; u++) {
            int idx = tid + u * 256;
            int r = idx >> 5, c8 = idx & 31;
            *(uint4*)&Bs[buf][r][c8 * 8] = br[u];
        }
    };

    float acc[MF][NF][4];
#pragma unroll
    for (int i = 0; i < MF; i++)
#pragma unroll
        for (int j = 0; j < NF; j++)
#pragma unroll
            for (int q = 0; q < 4; q++) acc[i][j][q] = 0.f;

    auto comp = [&](int buf) {
#pragma unroll
        for (int kk = 0; kk < 2; kk++) {
            uint32_t af[MF][4], bf[NF][2];
#pragma unroll
            for (int mi = 0; mi < MF; mi++) {
                int row = mi * 16 + (lane & 15);
                int col = kk * 16 + (lane >> 4) * 8;
                uint32_t ad = (uint32_t)__cvta_generic_to_shared(&As[buf][row][col]);
                ldm_x4(af[mi][0], af[mi][1], af[mi][2], af[mi][3], ad);
            }
#pragma unroll
            for (int nj = 0; nj < NF; nj++) {
                int r = kk * 16 + (lane & 15), c = wn + nj * 8;
                uint32_t ad = (uint32_t)__cvta_generic_to_shared(&Bs[buf][r][c]);
                ldm_x2t(bf[nj][0], bf[nj][1], ad);
            }
#pragma unroll
            for (int mi = 0; mi < MF; mi++)
#pragma unroll
                for (int nj = 0; nj < NF; nj++)
                    mma_bf16(acc[mi][nj], af[mi], bf[nj]);
        }
    };

    ldg(0); sts(0); __syncthreads();
    int buf = 0;
    for (int kt = 1; kt < 24; kt++) {
        ldg(kt);
        comp(buf);
        sts(buf ^ 1);
        __syncthreads();
        buf ^= 1;
    }
    comp(buf);

#pragma unroll
    for (int mi = 0; mi < MF; mi++) {
        int d0 = mi * 16 + (lane >> 2);
#pragma unroll
        for (int p = 0; p < 2; p++) {
            int d = d0 + p * 8;
            int c = h * 48 + d;
            const float* xr = x + ((long long)(t * 16 + b) * 384 + c) * 256;
            float* orow = g_o + (long long)c * COLS + t * 4096 + b * 256;
#pragma unroll
            for (int nj = 0; nj < NF; nj++) {
                int n = wn + nj * 8 + (lane & 3) * 2;
                float2 xv = *(const float2*)&xr[n];
                float2 v = {acc[mi][nj][p * 2 + 0] + xv.x, acc[mi][nj][p * 2 + 1] + xv.y};
                *(float2*)&orow[n] = v;
            }
        }
    }
}

// ---------------- fp32 GEMM (proj only — exact numerics) ----------------
template<int BM, int BN, int BK, int TM, int TN>
__global__ void __launch_bounds__(256, 2)
gemm_f32(int M, int N, int K,
         const float* __restrict__ A, int lda,
         const float* __restrict__ B, int ldb,
         float* __restrict__ C, int ldc,
         const float* __restrict__ bias)
{
    constexpr int TX = BN / TN, TY = BM / TM, NT = TX * TY;
    constexpr int A4 = BM * BK / 4, B4 = BK * BN / 4;
    constexpr int APT = A4 / NT, BPT = B4 / NT;
    __shared__ __align__(16) float As[2][BK][BM + 4];
    __shared__ __align__(16) float Bs[2][BK][BN];
    const int tx = threadIdx.x, ty = threadIdx.y;
    const int tid = ty * TX + tx;
    const int row0 = blockIdx.y * BM, col0 = blockIdx.x * BN;
    float4 aR[APT], bR[BPT];
    auto ldg = [&](int k0) {
#pragma unroll
        for (int u = 0; u < APT; u++) {
            int idx = tid + u * NT;
            int r = idx / (BK / 4), c4 = idx % (BK / 4);
            aR[u] = *(const float4*)&A[(long long)(row0 + r) * lda + k0 + c4 * 4];
        }
#pragma unroll
        for (int u = 0; u < BPT; u++) {
            int idx = tid + u * NT;
            int kk = idx / (BN / 4), n4 = idx % (BN / 4);
            bR[u] = *(const float4*)&B[(long long)(k0 + kk) * ldb + col0 + n4 * 4];
        }
    };
    auto sts = [&](int buf) {
#pragma unroll
        for (int u = 0; u < APT; u++) {
            int idx = tid + u * NT;
            int r = idx / (BK / 4), c4 = idx % (BK / 4);
            As[buf][c4 * 4 + 0][r] = aR[u].x;
            As[buf][c4 * 4 + 1][r] = aR[u].y;
            As[buf][c4 * 4 + 2][r] = aR[u].z;
            As[buf][c4 * 4 + 3][r] = aR[u].w;
        }
#pragma unroll
        for (int u = 0; u < BPT; u++) {
            int idx = tid + u * NT;
            int kk = idx / (BN / 4), n4 = idx % (BN / 4);
            *(float4*)&Bs[buf][kk][n4 * 4] = bR[u];
        }
    };
    float acc[TM][TN];
#pragma unroll
    for (int i = 0; i < TM; i++)
#pragma unroll
        for (int j = 0; j < TN; j++) acc[i][j] = 0.f;
    auto comp = [&](int buf) {
#pragma unroll
        for (int kk = 0; kk < BK; kk++) {
            float a[TM], b[TN];
#pragma unroll
            for (int i4 = 0; i4 < TM / 4; i4++) {
                float4 v = *(const float4*)&As[buf][kk][ty * TM + i4 * 4];
                a[i4*4+0]=v.x; a[i4*4+1]=v.y; a[i4*4+2]=v.z; a[i4*4+3]=v.w;
            }
#pragma unroll
            for (int j4 = 0; j4 < TN / 4; j4++) {
                float4 v = *(const float4*)&Bs[buf][kk][tx * TN + j4 * 4];
                b[j4*4+0]=v.x; b[j4*4+1]=v.y; b[j4*4+2]=v.z; b[j4*4+3]=v.w;
            }
#pragma unroll
            for (int i = 0; i < TM; i++)
#pragma unroll
                for (int j = 0; j < TN; j++)
                    acc[i][j] = fmaf(a[i], b[j], acc[i][j]);
        }
    };
    ldg(0); sts(0); __syncthreads();
    const int nit = K / BK;
    int buf = 0;
    for (int it = 1; it < nit; it++) {
        ldg(it * BK); comp(buf); sts(buf ^ 1); __syncthreads(); buf ^= 1;
    }
    comp(buf);
#pragma unroll
    for (int i = 0; i < TM; i++) {
        int r = row0 + ty * TM + i;
        float bv = bias ? bias[r] : 0.f;
#pragma unroll
        for (int j4 = 0; j4 < TN / 4; j4++) {
            float4 v;
            v.x = acc[i][j4*4+0] + bv; v.y = acc[i][j4*4+1] + bv;
            v.z = acc[i][j4*4+2] + bv; v.w = acc[i][j4*4+3] + bv;
            *(float4*)&C[(long long)r * ldc + col0 + tx * TN + j4 * 4] = v;
        }
    }
}

// ---------------- split helper ----------------
__device__ __forceinline__ void split3f(float x, __nv_bfloat16& h, __nv_bfloat16& m, __nv_bfloat16& l)
{
    __nv_bfloat16 bh = __float2bfloat16(x);
    float r1 = x - __bfloat162float(bh);
    __nv_bfloat16 bm = __float2bfloat16(r1);
    float r2 = r1 - __bfloat162float(bm);
    h = bh; m = bm; l = __float2bfloat16(r2);
}

// ---------------- BN folding ----------------
__global__ void fold_weights(const float* __restrict__ wq, const float* __restrict__ wk,
                             const float* __restrict__ wv, const float* __restrict__ pw,
                             const float* __restrict__ pb, const float* __restrict__ kbn,
                             const float* __restrict__ vbn, const float* __restrict__ pbn,
                             const float* __restrict__ dstw, const float* __restrict__ dbn)
{
    int i = blockIdx.x * blockDim.x + threadIdx.x;
    if (i == 0) g_cnt[0] = 0.f;
    if (i < 3 * KC * KC) {
        int rr = i / KC, c = i % KC;
        float w;
        if (rr < KC) w = wq[rr * KC + c];
        else if (rr < 2 * KC) { int d = rr - KC;     w = kbn[d] * rsqrtf(kbn[3*KC + d] + 1e-5f) * wk[d * KC + c]; }
        else                  { int d = rr - 2 * KC; w = vbn[d] * rsqrtf(vbn[3*KC + d] + 1e-5f) * wv[d * KC + c]; }
        g_wqkv[i] = w;
    }
    if (i < KC * KC) {
        int d = i / KC;
        g_wpf[i] = pbn[d] * rsqrtf(pbn[3*KC + d] + 1e-5f) * pw[i];
    }
    if (i < 3 * KC) {
        float bvv;
        if (i < KC) bvv = 0.f;
        else if (i < 2 * KC) { int d = i - KC;     float inv = kbn[d] * rsqrtf(kbn[3*KC+d] + 1e-5f); bvv = kbn[KC + d] - inv * kbn[2*KC + d]; }
        else                 { int d = i - 2 * KC; float inv = vbn[d] * rsqrtf(vbn[3*KC+d] + 1e-5f); bvv = vbn[KC + d] - inv * vbn[2*KC + d]; }
        g_bqkv[i] = bvv;
    }
    if (i < KC) {
        float inv = pbn[i] * rsqrtf(pbn[3*KC + i] + 1e-5f);
        g_bp[i] = pbn[KC + i] + inv * (pb[i] - pbn[2*KC + i]);
    }
    if (i < KD * KD) {
        int e = i / KD, d = i % KD;
        float inv = dbn[e] * rsqrtf(dbn[3*KD + e] + 1e-5f);
        float wf = inv * dstw[i];
        g_dw[i] = wf;
        g_dwT[d * KD + e] = wf;
    }
    if (i < KD) {
        float inv = dbn[i] * rsqrtf(dbn[3*KD + i] + 1e-5f);
        g_db[i] = dbn[KD + i] - inv * dbn[2*KD + i];
    }
}

__global__ void split_qkv()
{
    int i = blockIdx.x * blockDim.x + threadIdx.x;
    if (i >= 3 * KC * KC) return;
    int r = i / KC, c = i % KC;
    __nv_bfloat16 h, m, l;
    split3f(g_wqkv[i], h, m, l);
    __nv_bfloat16* row = g_wqkv3 + (long long)r * 1152;
    row[c] = h; row[KC + c] = m; row[2 * KC + c] = l;
}

__global__ void split_tim(const float* __restrict__ timw)
{
    int i = blockIdx.x * blockDim.x + threadIdx.x;
    if (i >= KC * KC * 5) return;
    int r = i / (KC * 5), c = i % (KC * 5);
    __nv_bfloat16 h, m, l;
    split3f(timw[i], h, m, l);
    __nv_bfloat16* row = g_timw3 + (long long)r * 5760;
    row[c] = h; row[1920 + c] = m; row[3840 + c] = l;
}

// ---------------- LIF kernels ----------------
__global__ void lif_in(const float* __restrict__ x)
{
    int i = blockIdx.x * blockDim.x + threadIdx.x;
    if (i >= SZ_XT) return;
    int c = i >> 12, j = i & 4095, b = j >> 8, n = j & 255;
    const float* xp = x + ((long long)b * KC + c) * KN + n;
    __nv_bfloat16* o = g_xsb + (long long)c * COLS + j;
    float v = 0.f;
#pragma unroll
    for (int t = 0; t < KT; t++) {
        float xv = xp[(long long)t * KB * KC * KN];
        v += (xv - v) * 0.5f;
        float s = (v >= 1.f) ? 1.f : 0.f;
        o[t * TCOL] = __float2bfloat16(s);
        v *= (1.f - s);
    }
}

// fused LIF over q|k|v; region 0 seeds TIM z-state (t=0), region 2 writes out_v
__global__ void lif_qkv_fused(float* __restrict__ outv)
{
    int i = blockIdx.x * blockDim.x + threadIdx.x;
    if (i >= 3 * SZ_XT) return;
    int region = i / SZ_XT;
    int il = i - region * SZ_XT;
    int c = il >> 12, j = il & 4095;
    float vth = (region == 0) ? 0.05f : 1.0f;
    float* buf = g_qkv + (long long)region * SZ_X;
    long long o = ((long long)c) * COLS + j;
    int b = j >> 8, n = j & 255;
    int h = c / KD, d = c - h * KD;
    float v = 0.f;
#pragma unroll
    for (int t = 0; t < KT; t++) {
        long long a = o + t * TCOL;
        float xv = buf[a];
        v += (xv - v) * 0.5f;
        float s = (v >= vth) ? 1.f : 0.f;
        buf[a] = s;
        v *= (1.f - s);
        if (region == 0 && t == 0)
            g_zt[c * TCOL + j] = __float2bfloat16(5.0f * s);
        if (region == 2)
            outv[(((long long)(t * KB + b) * KH + h) * KN + n) * KD + d] = s;
    }
}

// ---------------- TIM ----------------
// full im2col (only needed once, at ti=1; also writes the always-zero boundary slots)
__global__ void im2col_k()
{
    int i = blockIdx.x * blockDim.x + threadIdx.x;
    if (i >= SZ_COL) return;
    int j = i & 4095, r = i >> 12;
    int kk = r % 5, ci = r / 5;
    int n = j & 255;
    int n2 = n + kk - 2;
    __nv_bfloat16 v = __float2bfloat16(0.f);
    if (n2 >= 0 && n2 < KN) v = g_zt[ci * TCOL + (j - n) + n2];
    g_colb[i] = v;
}

// tim update with direct scatter into colb (valid slots only; boundary slots
// stay zero from the ti=1 im2col — they are zero in every iteration).
__global__ void tim_update_scatter(int ti, const float* __restrict__ timb)
{
    int i = blockIdx.x * blockDim.x + threadIdx.x;
    if (i >= SZ_XT) return;
    int c = i >> 12, j = i & 4095;
    int n = j & 255;
    float cv = 0.2f * g_cb[i] + timb[c];
    float s = (cv * 0.5f >= 0.3f) ? 1.f : 0.f;
    long long qa = (long long)c * COLS + ti * TCOL + j;
    float q = g_qkv[qa];
    float xt = s * 0.6f + q * 0.4f;
    g_qkv[qa] = xt;
    __nv_bfloat16 zv = __float2bfloat16(3.0f * s + 2.0f * q);
#pragma unroll
    for (int kk = 0; kk < 5; kk++) {
        int ns = n + 2 - kk;
        if (ns >= 0 && ns < KN)
            g_colb[(long long)(c * 5 + kk) * TCOL + (j - n) + ns] = zv;
    }
}

// final TIM LIF: writes q spikes DIRECTLY into qhT head layout (bf16) + spike count
__global__ void tim_final_qh()
{
    int i = blockIdx.x * blockDim.x + threadIdx.x;
    int cnt = 0;
    if (i < SZ_XT) {
        int c = i >> 12, j = i & 4095;
        int b = j >> 8, n = j & 255;
        int h = c / KD, d = c - h * KD;
        const float* q = g_qkv + (long long)c * COLS + j;
        float v = 0.f;
#pragma unroll
        for (int t = 0; t < KT; t++) {
            float xv = q[t * TCOL];
            v += (xv - v) * 0.5f;
            float s = (v >= 0.5f) ? 1.f : 0.f;
            int z = h * 64 + t * 16 + b;
            g_qhT[((long long)z * KD + d) * KN + n] = __float2bfloat16(s);
            cnt += (int)s;
            v *= (1.f - s);
        }
    }
#pragma unroll
    for (int o = 16; o > 0; o >>= 1) cnt += __shfl_down_sync(0xffffffffu, cnt, o);
    if ((threadIdx.x & 31) == 0 && cnt) atomicAdd(&g_cnt[0], (float)cnt);
}

__global__ void c1_kernel()
{
    float mean = g_cnt[0] / 6291456.0f;
    g_c1[0] = fminf(1.0f / sqrtf(mean * 48.0f + 1e-6f), 10.0f);
}

// ---------------- dst conv (48x48): ktT3 [z][m][sp*48+e], vtT3 [z][d][sp*256+m] ----------------
__global__ void kt_gemm()
{
    int z = blockIdx.x;                 // z = h*64 + t*16 + b
    int h = z >> 6, t = (z >> 4) & 3, b = z & 15;
    int m = threadIdx.x;
    __shared__ float A[KD * KD];
    __shared__ float bs[KD];
    for (int idx = m; idx < KD * KD; idx += 256) A[idx] = g_dw[idx];
    if (m < KD) bs[m] = g_db[m];
    __syncthreads();
    const float* kp = g_qkv + SZ_X + (long long)(h * KD) * COLS + t * TCOL + b * KN + m;
    float kd[KD];
#pragma unroll
    for (int d = 0; d < KD; d++) kd[d] = kp[(long long)d * COLS];
    float s[KD];
#pragma unroll
    for (int e = 0; e < KD; e++) {
        float acc = bs[e];
#pragma unroll
        for (int d = 0; d < KD; d++) acc = fmaf(A[e * KD + d], kd[d], acc);
        s[e] = acc;
    }
    uint2* dst = (uint2*)(g_kt3 + (long long)z * (256 * 144) + m * 144);
#pragma unroll
    for (int sp = 0; sp < 3; sp++) {
#pragma unroll
        for (int w = 0; w < 12; w++) {
            __nv_bfloat16 t0 = __float2bfloat16(s[w*4+0]); s[w*4+0] -= __bfloat162float(t0);
            __nv_bfloat16 t1 = __float2bfloat16(s[w*4+1]); s[w*4+1] -= __bfloat162float(t1);
            __nv_bfloat16 t2 = __float2bfloat16(s[w*4+2]); s[w*4+2] -= __bfloat162float(t2);
            __nv_bfloat16 t3 = __float2bfloat16(s[w*4+3]); s[w*4+3] -= __bfloat162float(t3);
            __nv_bfloat162 p01 = __halves2bfloat162(t0, t1);
            __nv_bfloat162 p23 = __halves2bfloat162(t2, t3);
            uint2 u;
            u.x = *reinterpret_cast<uint32_t*>(&p01);
            u.y = *reinterpret_cast<uint32_t*>(&p23);
            dst[sp * 12 + w] = u;
        }
    }
}

__global__ void vt_gemm()
{
    int z = blockIdx.x;
    int h = z >> 6, t = (z >> 4) & 3, b = z & 15;
    int m = threadIdx.x;
    __shared__ float BT[KD * KD];
    __shared__ float bs[KD];
    for (int idx = m; idx < KD * KD; idx += 256) BT[idx] = g_dwT[idx];
    if (m < KD) bs[m] = g_db[m];
    __syncthreads();
    const float* vp = g_qkv + 2 * SZ_X + (long long)(h * KD) * COLS + t * TCOL + b * KN + m;
    float r[KD];
#pragma unroll
    for (int d = 0; d < KD; d++) r[d] = vp[(long long)d * COLS];
    __nv_bfloat16* Cp = g_vt3 + (long long)z * (48 * 768) + m;
#pragma unroll
    for (int e = 0; e < KD; e++) {
        float s = bs[e];
#pragma unroll
        for (int d = 0; d < KD; d++) s = fmaf(r[d], BT[d * KD + e], s);
        __nv_bfloat16 hh = __float2bfloat16(s); s -= __bfloat162float(hh);
        __nv_bfloat16 mm = __float2bfloat16(s); s -= __bfloat162float(mm);
        __nv_bfloat16 ll = __float2bfloat16(s);
        Cp[e * 768]       = hh;
        Cp[e * 768 + 256] = mm;
        Cp[e * 768 + 512] = ll;
    }
}

// ---------------- final LIF ----------------
__global__ void final_lif(float* __restrict__ out)
{
    int i = blockIdx.x * blockDim.x + threadIdx.x;
    if (i >= SZ_XT) return;
    int c = i >> 12, j = i & 4095, b = j >> 8, n = j & 255;
    const float* p = g_p + (long long)c * COLS + j;
    float* o = out + ((long long)b * KC + c) * KN + n;
    float v = 0.f;
#pragma unroll
    for (int t = 0; t < KT; t++) {
        float xv = p[t * TCOL];
        v += (xv - v) * 0.5f;
        float s = (v >= 1.f) ? 1.f : 0.f;
        o[(long long)t * KB * KC * KN] = s;
        v *= (1.f - s);
    }
}

// ---------------- host launcher ----------------
extern "C" void kernel_launch(void* const* d_in, const int* in_sizes, int n_in,
                              void* d_out, int out_size)
{
    (void)in_sizes; (void)n_in; (void)out_size;
    const float* x    = (const float*)d_in[0];
    const float* wq   = (const float*)d_in[1];
    const float* wk   = (const float*)d_in[2];
    const float* wv   = (const float*)d_in[3];
    const float* kbn  = (const float*)d_in[4];
    const float* vbn  = (const float*)d_in[5];
    const float* dstw = (const float*)d_in[6];
    const float* dbn  = (const float*)d_in[7];
    const float* pw   = (const float*)d_in[8];
    const float* pb   = (const float*)d_in[9];
    const float* pbn  = (const float*)d_in[10];
    const float* timw = (const float*)d_in[11];
    const float* timb = (const float*)d_in[12];
    float* out   = (float*)d_out;
    float* out_v = out + SZ_X;

    float *pqkv, *pcb, *po, *pp, *pbp, *pbqkv, *pwpf;
    __nv_bfloat16 *pxsb, *pcolb, *pwqkv3, *ptimw3;
    cudaGetSymbolAddress((void**)&pqkv,   g_qkv);
    cudaGetSymbolAddress((void**)&pcb,    g_cb);
    cudaGetSymbolAddress((void**)&po,     g_o);
    cudaGetSymbolAddress((void**)&pp,     g_p);
    cudaGetSymbolAddress((void**)&pbp,    g_bp);
    cudaGetSymbolAddress((void**)&pbqkv,  g_bqkv);
    cudaGetSymbolAddress((void**)&pwpf,   g_wpf);
    cudaGetSymbolAddress((void**)&pxsb,   g_xsb);
    cudaGetSymbolAddress((void**)&pcolb,  g_colb);
    cudaGetSymbolAddress((void**)&pwqkv3, g_wqkv3);
    cudaGetSymbolAddress((void**)&ptimw3, g_timw3);

    const int TB = 256;

    fold_weights<<<(3 * KC * KC + TB - 1) / TB, TB>>>(wq, wk, wv, pw, pb, kbn, vbn, pbn, dstw, dbn);
    split_qkv<<<(3 * KC * KC + TB - 1) / TB, TB>>>();
    split_tim<<<(KC * KC * 5 + TB - 1) / TB, TB>>>(timw);
    lif_in<<<SZ_XT / TB, TB>>>(x);

    // fused q|k|v: M=1152, N=16384, K'=1152, B wraps every 384 — occupancy 2
    gemm_bf16<128,128,32,64,32,0,384,1,2><<<dim3(128, 9, 1), 256>>>(
        1152, pwqkv3, 1152, 0, pxsb, COLS, 0, pqkv, COLS, 0, pbqkv);

    // fused LIF (+ TIM z seed for t=0, + out_v writes for v)
    lif_qkv_fused<<<3 * SZ_XT / TB, TB>>>(out_v);

    // TIM: sequential over t = 1..3 — im2col only once; updates scatter into colb
    for (int ti = 1; ti < KT; ti++) {
        if (ti == 1) im2col_k<<<SZ_COL / TB, TB>>>();
        gemm_bf16<64,128,32,32,32,0,1920,0,2><<<dim3(32, 6, 1), 256>>>(
            5760, ptimw3, 5760, 0, pcolb, TCOL, 0, pcb, TCOL, 0, nullptr);
        tim_update_scatter<<<SZ_XT / TB, TB>>>(ti, timb);
    }
    // final TIM LIF writes qhT directly
    tim_final_qh<<<SZ_XT / TB, TB>>>();
    c1_kernel<<<1, 1>>>();

    // dst conv + shared BN (z = h*64 + t*16 + b)
    kt_gemm<<<512, 256>>>();
    vt_gemm<<<512, 256>>>();

    // fused attn scores + LIF
    attn_lif_fused<<<dim3(4, 4, 128), 256>>>();

    // fused outT GEMM + identity add -> g_o (occ 2)
    out_fused<<<512, 256>>>(x);

    // proj (exact fp32 FFMA): 384 x 16384 x 384
    gemm_f32<128,128,16,8,8><<<dim3(128, 3, 1), dim3(16, 16)>>>(
        KC, COLS, KC, pwpf, KC, po, COLS, pp, COLS, pbp);

    final_lif<<<SZ_XT / TB, TB>>>(out);
}